// round 14
// baseline (speedup 1.0000x reference)
#include <cuda_runtime.h>
#include <cuda_bf16.h>
#include <cuda_fp16.h>
#include <cstdint>

// Problem constants
#define BB 2
#define NN 2048
#define DIMX 64
#define HH 8
#define DD 512            // per-head dim
#define INNER 4096
#define SCALE 0.125f
#define MASKV -1e9f

#define OUT_ELEMS   (BB*NN*DIMX)          // 262144
#define PRE_ELEMS   (BB*HH*NN*NN)         // 67108864

#define NROWS (BB*HH*NN)   // 32768
#define NZ    (BB*HH)      // 16
#define MAXS  512

// Scratch
__device__ __half g_qh[BB*HH*NN*DD];
__device__ __half g_ql[BB*HH*NN*DD];
__device__ __half g_kh[BB*HH*NN*DD];
__device__ __half g_vh[BB*HH*NN*DD];
__device__ __half g_vl[BB*HH*NN*DD];
__device__ __half g_xh[4096*64];
__device__ __half g_xl[4096*64];
__device__ __half g_wh[12288*64];
__device__ __half g_wl[12288*64];
__device__ __half g_wo[HH*64*DD];
__device__ float  g_p[(size_t)NZ * NN * 64];
__device__ float  g_psum[NZ * 64];
__device__ float  g_psumP[NZ][8][64];
__device__ int    g_mask[BB*NN];
__device__ int    g_slot[BB*NN];         // n -> compact slot (-1 if masked)
__device__ int    g_rowmap[BB][NN];      // compact slot -> n (valid rows)
__device__ int    g_maskedmap[BB][NN];   // masked slot -> n (masked rows)
__device__ int    g_validcnt[BB];
__device__ int    g_si[(size_t)NROWS * MAXS];
__device__ float  g_sw[(size_t)NROWS * MAXS];
__device__ int    g_cnt[NROWS];

// ===========================================================================
// Helpers
// ===========================================================================
__device__ __forceinline__ uint32_t smem_u32(const void* p) {
    uint32_t r;
    asm("{ .reg .u64 t; cvta.to.shared.u64 t, %1; cvt.u32.u64 %0, t; }" : "=r"(r) : "l"(p));
    return r;
}
__device__ __forceinline__ void ldsm_x4(uint32_t* r, uint32_t addr) {
    asm volatile("ldmatrix.sync.aligned.m8n8.x4.shared.b16 {%0,%1,%2,%3}, [%4];"
        : "=r"(r[0]), "=r"(r[1]), "=r"(r[2]), "=r"(r[3]) : "r"(addr));
}
__device__ __forceinline__ void mma_f16(float* c, const uint32_t* a, const uint32_t* b) {
    asm volatile("mma.sync.aligned.m16n8k16.row.col.f32.f16.f16.f32 "
        "{%0,%1,%2,%3}, {%4,%5,%6,%7}, {%8,%9}, {%0,%1,%2,%3};"
        : "+f"(c[0]), "+f"(c[1]), "+f"(c[2]), "+f"(c[3])
        : "r"(a[0]), "r"(a[1]), "r"(a[2]), "r"(a[3]), "r"(b[0]), "r"(b[1]));
}
#define CP16(saddr, gptr) \
    asm volatile("cp.async.cg.shared.global [%0], [%1], 16;" :: "r"(saddr), "l"(gptr))
#define CP_COMMIT() asm volatile("cp.async.commit_group;")
#define CP_WAIT2()  asm volatile("cp.async.wait_group 2;")
#define CP_WAIT1()  asm volatile("cp.async.wait_group 1;")
#define CP_WAIT0()  asm volatile("cp.async.wait_group 0;")

__device__ __forceinline__ uint32_t swz(uint32_t r, uint32_t kb) {
    uint32_t off = r * 64u + kb;
    return off ^ ((off >> 3) & 0x70u);
}
__device__ __forceinline__ void split4h(float4 v, uint2& hh, uint2& ll) {
    __half2 h01 = __floats2half2_rn(v.x, v.y);
    __half2 h23 = __floats2half2_rn(v.z, v.w);
    float2 f01 = __half22float2(h01);
    float2 f23 = __half22float2(h23);
    __half2 l01 = __floats2half2_rn(v.x - f01.x, v.y - f01.y);
    __half2 l23 = __floats2half2_rn(v.z - f23.x, v.w - f23.y);
    hh.x = *(uint32_t*)&h01; hh.y = *(uint32_t*)&h23;
    ll.x = *(uint32_t*)&l01; ll.y = *(uint32_t*)&l23;
}

// ===========================================================================
// prep_mask + compact merged (single block)
// ===========================================================================
__global__ __launch_bounds__(256) void prep_compact_kernel(const unsigned char* __restrict__ raw) {
    __shared__ int cnt_f32, cnt_gt1;
    __shared__ int ps[256];
    if (threadIdx.x == 0) { cnt_f32 = 0; cnt_gt1 = 0; }
    __syncthreads();
    const unsigned int* u = (const unsigned int*)raw;
    int lf = 0, lg = 0;
    for (int i = threadIdx.x; i < 1024; i += blockDim.x) {
        unsigned int v = u[i];
        if (v == 0x3f800000u) lf++;
        else if (v > 1u) lg++;
    }
    atomicAdd(&cnt_f32, lf);
    atomicAdd(&cnt_gt1, lg);
    __syncthreads();
    int mode;
    if (cnt_f32 > 64) mode = 2;
    else if (cnt_gt1 > 64) mode = 1;
    else mode = 0;
    for (int i = threadIdx.x; i < BB*NN; i += blockDim.x) {
        int m;
        if (mode == 2)      m = (((const unsigned int*)raw)[i] != 0u) ? 1 : 0;
        else if (mode == 1) m = raw[i] ? 1 : 0;
        else                m = (((const int*)raw)[i] != 0) ? 1 : 0;
        g_mask[i] = m;
    }
    __syncthreads();

    for (int b = 0; b < BB; b++) {
        const int base_n = threadIdx.x * 8;
        int m[8], s = 0;
#pragma unroll
        for (int i = 0; i < 8; i++) { m[i] = g_mask[b * NN + base_n + i]; s += m[i]; }
        ps[threadIdx.x] = s;
        __syncthreads();
        for (int off = 1; off < 256; off <<= 1) {
            int v = ps[threadIdx.x];
            int u2 = (threadIdx.x >= off) ? ps[threadIdx.x - off] : 0;
            __syncthreads();
            ps[threadIdx.x] = v + u2;
            __syncthreads();
        }
        int pos = threadIdx.x ? ps[threadIdx.x - 1] : 0;
#pragma unroll
        for (int i = 0; i < 8; i++) {
            int n = base_n + i;
            if (m[i]) {
                g_rowmap[b][pos] = n;
                g_slot[b * NN + n] = pos;
                pos++;
            } else {
                g_maskedmap[b][n - pos] = n;
                g_slot[b * NN + n] = -1;
            }
        }
        if (threadIdx.x == 255) g_validcnt[b] = ps[255];
        __syncthreads();
    }
}

// ===========================================================================
// conv_all: fused conv_x (blocks 0..255), conv_w (256..1023), conv_wo (1024..1087)
// ===========================================================================
__global__ __launch_bounds__(256) void conv_all_kernel(
    const float* __restrict__ X,
    const float* __restrict__ Wq, const float* __restrict__ Wk, const float* __restrict__ Wv,
    const float* __restrict__ Wo)
{
    __shared__ float sh[64 * 65];
    const int bx = blockIdx.x;
    if (bx < 256) {
        int idx = bx * 256 + threadIdx.x;
        int m = idx >> 4;
        int k = (idx & 15) * 4;
        float4 v = ((const float4*)X)[idx];
        uint2 hh, ll;
        split4h(v, hh, ll);
        size_t tb = ((size_t)(m >> 7) * 2 + (k >> 5)) * 8192;
        uint32_t so = swz((uint32_t)(m & 127), (uint32_t)(k & 31) * 2);
        *(uint2*)((char*)g_xh + tb + so) = hh;
        *(uint2*)((char*)g_xl + tb + so) = ll;
    } else if (bx < 1024) {
        float (*t)[33] = (float(*)[33])sh;
        const int i = bx - 256;
        const int kt = i / 384;
        const int n0 = (i % 384) * 32;
        const float* W = (n0 < 4096) ? Wq : (n0 < 8192) ? Wk : Wv;
        const int nl0 = n0 & 4095;
        const int tx = threadIdx.x & 31, ty8 = threadIdx.x >> 5;
#pragma unroll
        for (int j = 0; j < 4; j++) {
            int kk = ty8 + j * 8;
            t[kk][tx] = W[(size_t)(kt * 32 + kk) * 4096 + nl0 + tx];
        }
        __syncthreads();
        const int nn = threadIdx.x >> 3;
        const int k4 = (threadIdx.x & 7) * 4;
        float4 v = make_float4(t[k4][nn], t[k4+1][nn], t[k4+2][nn], t[k4+3][nn]);
        uint2 hh, ll;
        split4h(v, hh, ll);
        const int gn = n0 + nn;
        const int gk = kt * 32 + k4;
        size_t tb = ((size_t)(gn >> 7) * 2 + (gk >> 5)) * 8192;
        uint32_t so = swz((uint32_t)(gn & 127), (uint32_t)(gk & 31) * 2);
        *(uint2*)((char*)g_wh + tb + so) = hh;
        *(uint2*)((char*)g_wl + tb + so) = ll;
    } else {
        float (*t)[65] = (float(*)[65])sh;
        const int i = bx - 1024;
        const int h = i >> 3;
        const int d0 = (i & 7) * 64;
#pragma unroll
        for (int j = 0; j < 16; j++) {
            int idx = threadIdx.x + j * 256;
            int dl = idx >> 6, dc = idx & 63;
            t[dl][dc] = Wo[(size_t)(h * 512 + d0 + dl) * 64 + dc];
        }
        __syncthreads();
#pragma unroll
        for (int j = 0; j < 4; j++) {
            int jj = threadIdx.x + j * 256;
            int dc = jj >> 4;
            int d4 = (jj & 15) * 4;
            __half2 h01 = __floats2half2_rn(t[d4+0][dc], t[d4+1][dc]);
            __half2 h23 = __floats2half2_rn(t[d4+2][dc], t[d4+3][dc]);
            uint2 hv;
            hv.x = *(uint32_t*)&h01; hv.y = *(uint32_t*)&h23;
            const int d = d0 + d4;
            size_t tb = ((size_t)h * 16 + (d >> 5)) * 4096;
            uint32_t so = swz((uint32_t)dc, (uint32_t)(d & 31) * 2);
            *(uint2*)((char*)g_wo + tb + so) = hv;
        }
    }
}

// ===========================================================================
// proj_mma: C = x @ [Wq|Wk|Wv], 3-term fp16 split, 2-chunk pipelined.
// ===========================================================================
#define PROJ_SMEM 67584

__global__ __launch_bounds__(256, 2) void proj_mma()
{
    extern __shared__ char sm[];
    const uint32_t sbase = smem_u32(sm);
    const int tid = threadIdx.x;
    const int wid = tid >> 5, lane = tid & 31;
    const int wm = wid >> 2, wn = wid & 3;
    const int row0 = blockIdx.y * 128;
    const int col0 = blockIdx.x * 128;

    const char* xhB = (const char*)g_xh + (size_t)(blockIdx.y * 2) * 8192;
    const char* xlB = (const char*)g_xl + (size_t)(blockIdx.y * 2) * 8192;
    const char* whB = (const char*)g_wh + (size_t)(blockIdx.x * 2) * 8192;
    const char* wlB = (const char*)g_wl + (size_t)(blockIdx.x * 2) * 8192;

    auto issue = [&](int chk) {
        const uint32_t co = (uint32_t)chk * 8192;
#pragma unroll
        for (int k = 0; k < 2; k++) {
            uint32_t off = (uint32_t)(tid + k * 256) * 16;
            CP16(sbase + co + off,          xhB + co + off);
            CP16(sbase + 16384 + co + off,  xlB + co + off);
            CP16(sbase + 32768 + co + off,  whB + co + off);
            CP16(sbase + 49152 + co + off,  wlB + co + off);
        }
    };
    issue(0); CP_COMMIT();
    issue(1); CP_COMMIT();

    float acc[4][4][4];
#pragma unroll
    for (int mf = 0; mf < 4; mf++)
#pragma unroll
        for (int nf = 0; nf < 4; nf++)
#pragma unroll
            for (int r = 0; r < 4; r++) acc[mf][nf][r] = 0.f;

    const uint32_t a_row = (uint32_t)(wm * 64) + (lane & 15);
    const uint32_t a_kb  = ((lane >> 4) & 1) * 16;
    const uint32_t b_row = (uint32_t)(wn * 32) + ((lane >> 4) & 1) * 8 + (lane & 7);
    const uint32_t b_kb  = ((lane >> 3) & 1) * 16;

#pragma unroll
    for (int chk = 0; chk < 2; chk++) {
        if (chk == 0) CP_WAIT1(); else CP_WAIT0();
        __syncthreads();
        const uint32_t AH = sbase + (uint32_t)chk * 8192;
        const uint32_t AL = AH + 16384;
        const uint32_t BH = sbase + 32768 + (uint32_t)chk * 8192;
        const uint32_t BL = BH + 16384;
#pragma unroll
        for (int ks = 0; ks < 2; ks++) {
            const uint32_t kb0 = (uint32_t)ks * 32;
            uint32_t bh[4][2], bl[4][2];
#pragma unroll
            for (int p = 0; p < 2; p++) {
                uint32_t o = swz(b_row + p * 16, kb0 + b_kb);
                uint32_t t4[4];
                ldsm_x4(t4, BH + o);
                bh[2*p][0] = t4[0]; bh[2*p][1] = t4[1];
                bh[2*p+1][0] = t4[2]; bh[2*p+1][1] = t4[3];
                ldsm_x4(t4, BL + o);
                bl[2*p][0] = t4[0]; bl[2*p][1] = t4[1];
                bl[2*p+1][0] = t4[2]; bl[2*p+1][1] = t4[3];
            }
#pragma unroll
            for (int mf = 0; mf < 4; mf++) {
                uint32_t o = swz(a_row + mf * 16, kb0 + a_kb);
                uint32_t ah[4], al[4];
                ldsm_x4(ah, AH + o);
                ldsm_x4(al, AL + o);
#pragma unroll
                for (int nf = 0; nf < 4; nf++) {
                    mma_f16(acc[mf][nf], ah, bh[nf]);
                    mma_f16(acc[mf][nf], ah, bl[nf]);
                    mma_f16(acc[mf][nf], al, bh[nf]);
                }
            }
        }
    }

    // repack through SMEM
    __syncthreads();
    float* sacc = (float*)sm;   // [128][132]
    {
        const int rb = wm * 64 + (lane >> 2);
        const int cb = wn * 32 + (lane & 3) * 2;
#pragma unroll
        for (int mf = 0; mf < 4; mf++)
#pragma unroll
            for (int nf = 0; nf < 4; nf++)
#pragma unroll
                for (int rr = 0; rr < 2; rr++) {
                    int r = rb + mf * 16 + rr * 8;
                    int c = cb + nf * 8;
                    *(float2*)(sacc + r * 132 + c) =
                        make_float2(acc[mf][nf][rr*2+0], acc[mf][nf][rr*2+1]);
                }
    }
    __syncthreads();

    const int wsel = col0 >> 12;           // 0=Q 1=K 2=V
    const int dcol0 = col0 & 4095;
    const int r = tid >> 1;
    const int cH = (tid & 1) * 64;
    const int m = row0 + r;
    const int b = m >> 11, n = m & 2047;
    int nrow = n;
    if (wsel == 0) nrow = g_slot[b * NN + n];
    if (wsel != 0 || nrow >= 0) {
        const float* rowp = sacc + r * 132 + cH;
#pragma unroll
        for (int g = 0; g < 8; g++) {
            const int cg = cH + g * 8;
            const int col = dcol0 + cg;
            const int h = col >> 9, dd = col & 511;
            float4 e0 = *(const float4*)(rowp + g * 8);
            float4 e1 = *(const float4*)(rowp + g * 8 + 4);
            __half2 h0 = __floats2half2_rn(e0.x, e0.y);
            __half2 h1 = __floats2half2_rn(e0.z, e0.w);
            __half2 h2 = __floats2half2_rn(e1.x, e1.y);
            __half2 h3 = __floats2half2_rn(e1.z, e1.w);
            uint4 hv = make_uint4(*(uint32_t*)&h0, *(uint32_t*)&h1,
                                  *(uint32_t*)&h2, *(uint32_t*)&h3);
            size_t tb = (((size_t)(b*HH+h) * 16 + (nrow >> 7)) * 16 + (dd >> 5)) * 8192;
            uint32_t so = swz((uint32_t)(nrow & 127), (uint32_t)(dd & 31) * 2);
            if (wsel == 1) {
                *(uint4*)((char*)g_kh + tb + so) = hv;
            } else {
                float2 f0 = __half22float2(h0), f1 = __half22float2(h1);
                float2 f2 = __half22float2(h2), f3 = __half22float2(h3);
                __half2 l0 = __floats2half2_rn(e0.x - f0.x, e0.y - f0.y);
                __half2 l1 = __floats2half2_rn(e0.z - f1.x, e0.w - f1.y);
                __half2 l2 = __floats2half2_rn(e1.x - f2.x, e1.y - f2.y);
                __half2 l3 = __floats2half2_rn(e1.z - f3.x, e1.w - f3.y);
                uint4 lv = make_uint4(*(uint32_t*)&l0, *(uint32_t*)&l1,
                                      *(uint32_t*)&l2, *(uint32_t*)&l3);
                if (wsel == 0) {
                    *(uint4*)((char*)g_qh + tb + so) = hv;
                    *(uint4*)((char*)g_ql + tb + so) = lv;
                } else {
                    *(uint4*)((char*)g_vh + tb + so) = hv;
                    *(uint4*)((char*)g_vl + tb + so) = lv;
                }
            }
        }
    }
}

// ===========================================================================
// pvw_mma: P[z] = (Vh+Vl) @ Woh^T
// ===========================================================================
#define PVW_STAGE 20480u
#define PVW_SMEM (2 * 20480)

__global__ __launch_bounds__(256, 2) void pvw_mma()
{
    extern __shared__ char sm[];
    const uint32_t sbase = smem_u32(sm);
    const int tid = threadIdx.x;
    const int wid = tid >> 5, lane = tid & 31;
    const int wm = wid >> 1, wn = wid & 1;
    const int z = blockIdx.y, h = z & 7;
    const int nt = blockIdx.x;

    const char* vhB = (const char*)g_vh + (((size_t)z * 16 + nt) * 16) * 8192;
    const char* vlB = (const char*)g_vl + (((size_t)z * 16 + nt) * 16) * 8192;
    const char* woB = (const char*)g_wo + (size_t)(h * 16) * 4096;

    float acc[2][4][4];
#pragma unroll
    for (int mf = 0; mf < 2; mf++)
#pragma unroll
        for (int nf = 0; nf < 4; nf++)
#pragma unroll
            for (int r = 0; r < 4; r++) acc[mf][nf][r] = 0.f;

    auto issue = [&](int ch) {
        const uint32_t ss = sbase + (uint32_t)(ch & 1) * PVW_STAGE;
#pragma unroll
        for (int k = 0; k < 2; k++) {
            uint32_t off = (uint32_t)(tid + k * 256) * 16;
            CP16(ss + off,        vhB + (size_t)ch * 8192 + off);
            CP16(ss + 8192 + off, vlB + (size_t)ch * 8192 + off);
        }
        {
            uint32_t off = (uint32_t)tid * 16;
            CP16(ss + 16384 + off, woB + (size_t)ch * 4096 + off);
        }
    };

    issue(0); CP_COMMIT();

    const uint32_t a_row = (uint32_t)(wm * 32) + (lane & 15);
    const uint32_t a_kb  = ((lane >> 4) & 1) * 16;
    const uint32_t b_row = (uint32_t)(wn * 32) + ((lane >> 4) & 1) * 8 + (lane & 7);
    const uint32_t b_kb  = ((lane >> 3) & 1) * 16;

    for (int ch = 0; ch < 16; ++ch) {
        if (ch + 1 < 16) { issue(ch + 1); CP_COMMIT(); CP_WAIT1(); }
        else CP_WAIT0();
        __syncthreads();
        const uint32_t S = sbase + (uint32_t)(ch & 1) * PVW_STAGE;
        const uint32_t AH = S, AL = S + 8192, BH = S + 16384;
#pragma unroll
        for (int ks = 0; ks < 2; ks++) {
            const uint32_t kb0 = (uint32_t)ks * 32;
            uint32_t bh[4][2];
#pragma unroll
            for (int p = 0; p < 2; p++) {
                uint32_t o = swz(b_row + p * 16, kb0 + b_kb);
                uint32_t t4[4];
                ldsm_x4(t4, BH + o);
                bh[2*p][0] = t4[0]; bh[2*p][1] = t4[1];
                bh[2*p+1][0] = t4[2]; bh[2*p+1][1] = t4[3];
            }
#pragma unroll
            for (int mf = 0; mf < 2; mf++) {
                uint32_t o = swz(a_row + mf * 16, kb0 + a_kb);
                uint32_t ah[4], al[4];
                ldsm_x4(ah, AH + o);
                ldsm_x4(al, AL + o);
#pragma unroll
                for (int nf = 0; nf < 4; nf++) {
                    mma_f16(acc[mf][nf], ah, bh[nf]);
                    mma_f16(acc[mf][nf], al, bh[nf]);
                }
            }
        }
        __syncthreads();
    }

    const int r_lo = nt * 128 + wm * 32 + (lane >> 2);
    const int c_base = wn * 32 + (lane & 3) * 2;
    float* Pz = g_p + (size_t)z * NN * 64;
#pragma unroll
    for (int mf = 0; mf < 2; mf++) {
        int rg0 = r_lo + mf * 16;
#pragma unroll
        for (int nf = 0; nf < 4; nf++) {
            int cg = c_base + nf * 8;
            *(float2*)(Pz + (size_t)rg0 * 64 + cg)       = make_float2(acc[mf][nf][0], acc[mf][nf][1]);
            *(float2*)(Pz + (size_t)(rg0 + 8) * 64 + cg) = make_float2(acc[mf][nf][2], acc[mf][nf][3]);
        }
    }
}

// ===========================================================================
// psum: 2-phase parallel reduction
// ===========================================================================
__global__ __launch_bounds__(256) void psum_part_kernel()
{
    __shared__ float red[4][64];
    const int z = blockIdx.x, seg = blockIdx.y;
    const int d = threadIdx.x & 63, sub = threadIdx.x >> 6;
    const float* p = g_p + ((size_t)z * NN + seg * 256 + sub * 64) * 64 + d;
    float s = 0.f;
#pragma unroll 8
    for (int n = 0; n < 64; n++) s += p[(size_t)n * 64];
    red[sub][d] = s;
    __syncthreads();
    if (threadIdx.x < 64)
        g_psumP[z][seg][d] = red[0][d] + red[1][d] + red[2][d] + red[3][d];
}
__global__ __launch_bounds__(256) void psum_red_kernel()
{
    const int i = blockIdx.x * 256 + threadIdx.x;
    const int z = i >> 6, d = i & 63;
    float s = 0.f;
#pragma unroll
    for (int g = 0; g < 8; g++) s += g_psumP[z][g][d];
    g_psum[z * 64 + d] = s;
}

// ===========================================================================
// dots = scale*(Qh+Ql)@Kh^T (+col mask) on COMPACTED rows -> pre.
// Epilogue: SMEM repack -> coalesced float4 __stcs (valid + fill rows).
// ===========================================================================
#define DSTAGE 24576u
#define DOTS_SMEM (4 * 24576)

__global__ __launch_bounds__(256, 2) void dots_gemm(float* __restrict__ Out)
{
    extern __shared__ char sm[];
    __shared__ int cmask[128];
    const uint32_t sbase = smem_u32(sm);

    const int tid = threadIdx.x;
    const int wid = tid >> 5, lane = tid & 31;
    const int wm = wid >> 2, wn = wid & 3;
    const int z = blockIdx.z, b = z >> 3;
    const int row0 = blockIdx.y * 128, col0 = blockIdx.x * 128;

    const int cnt = g_validcnt[b];
    float* outz = Out + (size_t)z * NN * NN;

    if (row0 >= cnt) {
        // pure fill tile: coalesced MASKV rows through maskedmap
        const int r = tid >> 1;
        const int cH = (tid & 1) * 64;
        const int cr = row0 + r;
        const int orig = g_maskedmap[b][cr - cnt];
        float* rowp = outz + (size_t)orig * NN + col0 + cH;
        const float4 mv = make_float4(MASKV, MASKV, MASKV, MASKV);
#pragma unroll
        for (int g = 0; g < 16; g++)
            __stcs((float4*)(rowp + g * 4), mv);
        return;
    }

    if (tid < 128) cmask[tid] = g_mask[b * NN + col0 + tid];

    const char* qhB = (const char*)g_qh + (((size_t)z * 16 + blockIdx.y) * 16) * 8192;
    const char* qlB = (const char*)g_ql + (((size_t)z * 16 + blockIdx.y) * 16) * 8192;
    const char* khB = (const char*)g_kh + (((size_t)z * 16 + blockIdx.x) * 16) * 8192;

    float acc[4][4][4];
#pragma unroll
    for (int mf = 0; mf < 4; mf++)
#pragma unroll
        for (int nf = 0; nf < 4; nf++)
#pragma unroll
            for (int r = 0; r < 4; r++) acc[mf][nf][r] = 0.f;

    auto issue = [&](int ch) {
        const uint32_t ss = sbase + (uint32_t)(ch & 3) * DSTAGE;
        const char* q1 = qhB + (size_t)ch * 8192;
        const char* l1 = qlB + (size_t)ch * 8192;
        const char* k1 = khB + (size_t)ch * 8192;
#pragma unroll
        for (int k = 0; k < 2; k++) {
            uint32_t off = (uint32_t)(tid + k * 256) * 16;
            CP16(ss + off,         q1 + off);
            CP16(ss + 8192 + off,  l1 + off);
            CP16(ss + 16384 + off, k1 + off);
        }
    };

    issue(0); CP_COMMIT();
    issue(1); CP_COMMIT();
    issue(2); CP_COMMIT();

    const uint32_t a_row = (uint32_t)(wm * 64) + (lane & 15);
    const uint32_t a_kb  = ((lane >> 4) & 1) * 16;
    const uint32_t b_row = (uint32_t)(wn * 32) + ((lane >> 4) & 1) * 8 + (lane & 7);
    const uint32_t b_kb  = ((lane >> 3) & 1) * 16;

    for (int ch = 0; ch < 16; ++ch) {
        CP_WAIT2();
        __syncthreads();
        const uint32_t S = sbase + (uint32_t)(ch & 3) * DSTAGE;
        const uint32_t AH = S, AL = S + 8192, BH = S + 16384;
#pragma unroll
        for (int ks = 0; ks < 2; ks++) {
            const uint32_t kb0 = (uint32_t)ks * 32;
            uint32_t bh[4][2];
#pragma unroll
            for (int p = 0; p < 2; p++) {
                uint32_t o = swz(b_row + p * 16, kb0 + b_kb);
                uint32_t t4[4];
                ldsm_x4(t4, BH + o);
                bh[2*p][0] = t4[0]; bh[2*p][1] = t4[1];
                bh[2*p+1][0] = t4[2]; bh[2*p+1][1] = t4[3];
            }
#pragma unroll
            for (int mf = 0; mf < 4; mf++) {
                uint32_t o = swz(a_row + mf * 16, kb0 + a_kb);
                uint32_t ah[4], al[4];
                ldsm_x4(ah, AH + o);
                ldsm_x4(al, AL + o);
#pragma unroll
                for (int nf = 0; nf < 4; nf++) {
                    mma_f16(acc[mf][nf], ah, bh[nf]);
                    mma_f16(acc[mf][nf], al, bh[nf]);
                }
            }
        }
        if (ch + 3 < 16) issue(ch + 3);
        CP_COMMIT();
    }

    // ---- epilogue: repack accumulator through SMEM, then coalesced stores ----
    __syncthreads();
    float* sacc = (float*)sm;   // [128][132]
    {
        const int rb = wm * 64 + (lane >> 2);
        const int cb = wn * 32 + (lane & 3) * 2;
#pragma unroll
        for (int mf = 0; mf < 4; mf++)
#pragma unroll
            for (int nf = 0; nf < 4; nf++)
#pragma unroll
                for (int rr = 0; rr < 2; rr++) {
                    int r = rb + mf * 16 + rr * 8;
                    int c = cb + nf * 8;
                    *(float2*)(sacc + r * 132 + c) =
                        make_float2(acc[mf][nf][rr*2+0], acc[mf][nf][rr*2+1]);
                }
    }
    __syncthreads();

    const int r = tid >> 1;
    const int cH = (tid & 1) * 64;
    const int cr = row0 + r;
    float* rowp;
    if (cr < cnt) {
        const int orig = g_rowmap[b][cr];
        rowp = outz + (size_t)orig * NN + col0 + cH;
        const float* srow = sacc + r * 132 + cH;
#pragma unroll
        for (int g = 0; g < 16; g++) {
            float4 e = *(const float4*)(srow + g * 4);
            const int c = cH + g * 4;
            float4 v;
            v.x = cmask[c+0] ? e.x * SCALE : MASKV;
            v.y = cmask[c+1] ? e.y * SCALE : MASKV;
            v.z = cmask[c+2] ? e.z * SCALE : MASKV;
            v.w = cmask[c+3] ? e.w * SCALE : MASKV;
            __stcs((float4*)(rowp + g * 4), v);
        }
    } else {
        const int orig = g_maskedmap[b][cr - cnt];
        rowp = outz + (size_t)orig * NN + col0 + cH;
        const float4 mv = make_float4(MASKV, MASKV, MASKV, MASKV);
#pragma unroll
        for (int g = 0; g < 16; g++)
            __stcs((float4*)(rowp + g * 4), mv);
    }
}

// ===========================================================================
// entmax-1.5: streaming loads/stores; Newton with uniform early-exit
// ===========================================================================
__global__ __launch_bounds__(256) void entmax_kernel(
    const float* __restrict__ pre, float* __restrict__ att)
{
    const int wid = threadIdx.x >> 5, lane = threadIdx.x & 31;
    const size_t row = (size_t)blockIdx.x * 8 + wid;
    const int z = (int)(row >> 11), n = (int)(row & 2047), b = z >> 3;
    float4* o4 = (float4*)(att + row * NN);

    if (!g_mask[b * NN + n]) {
        const float P = 1.0f / 2048.0f;
        float4 u = make_float4(P, P, P, P);
#pragma unroll
        for (int i = 0; i < 16; i++) __stcs(&o4[lane + i * 32], u);
        if (lane == 0) g_cnt[row] = -1;
        return;
    }

    const float4* p4 = (const float4*)(pre + row * NN);
    float x[64];
    float mx = -3.0e38f;
#pragma unroll
    for (int i = 0; i < 16; i++) {
        float4 v = __ldcs(&p4[lane + i * 32]);
        x[4*i+0] = 0.5f * v.x; x[4*i+1] = 0.5f * v.y;
        x[4*i+2] = 0.5f * v.z; x[4*i+3] = 0.5f * v.w;
        mx = fmaxf(mx, fmaxf(fmaxf(x[4*i], x[4*i+1]), fmaxf(x[4*i+2], x[4*i+3])));
    }
#pragma unroll
    for (int off = 16; off; off >>= 1)
        mx = fmaxf(mx, __shfl_xor_sync(0xffffffffu, mx, off));
#pragma unroll
    for (int j = 0; j < 64; j++) x[j] -= mx;

    float tau = -1.0f;
#pragma unroll 1
    for (int it = 0; it < 12; ++it) {
        float s1 = 0.f, s2 = 0.f;
#pragma unroll
        for (int j = 0; j < 64; j++) {
            float d = fmaxf(x[j] - tau, 0.f);
            s1 += d;
            s2 = fmaf(d, d, s2);
        }
#pragma unroll
        for (int off = 16; off; off >>= 1) {
            s1 += __shfl_xor_sync(0xffffffffu, s1, off);
            s2 += __shfl_xor_sync(0xffffffffu, s2, off);
        }
        float step = (s1 > 1e-20f) ? (s2 - 1.0f) / (2.0f * s1) : 0.f;
        tau += step;
        if (fabsf(step) < 1e-6f) break;
    }

#pragma unroll
    for (int i = 0; i < 16; i++) {
        float4 w;
        float d;
        d = fmaxf(x[4*i+0] - tau, 0.f); w.x = d * d;
        d = fmaxf(x[4*i+1] - tau, 0.f); w.y = d * d;
        d = fmaxf(x[4*i+2] - tau, 0.f); w.z = d * d;
        d = fmaxf(x[4*i+3] - tau, 0.f); w.w = d * d;
        __stcs(&o4[lane + i * 32], w);
    }

    int cl = 0;
#pragma unroll
    for (int j = 0; j < 64; j++) cl += (x[j] > tau) ? 1 : 0;
    int v = cl;
#pragma unroll
    for (int d = 1; d < 32; d <<= 1) {
        int t = __shfl_up_sync(0xffffffffu, v, d);
        if (lane >= d) v += t;
    }
    int total = __shfl_sync(0xffffffffu, v, 31);
    int pos = v - cl;
    if (total <= MAXS) {
        int*   si = g_si + row * MAXS;
        float* sw = g_sw + row * MAXS;
#pragma unroll
        for (int i = 0; i < 16; i++)
#pragma unroll
            for (int c = 0; c < 4; c++) {
                int j = 4*i + c;
                if (x[j] > tau) {
                    float d = x[j] - tau;
                    si[pos] = 4*lane + 128*i + c;
                    sw[pos] = d * d;
                    pos++;
                }
            }
        if (lane == 31) g_cnt[row] = total;
    } else if (lane == 31) {
        g_cnt[row] = -2;
    }
}

// ===========================================================================
// Fused sparse attention-out
// ===========================================================================
__global__ __launch_bounds__(256) void af_kernel(
    const float* __restrict__ att, const float* __restrict__ bo, float* __restrict__ out)
{
    const int wid = threadIdx.x >> 5, lane = threadIdx.x & 31;
    const int gw = blockIdx.x * 8 + wid;
    const int b = gw >> 11, n = gw & 2047;
    const int dc = lane * 2;

    float2 acc;
    float2 bb = *(const float2*)(bo + dc);
    acc.x = bb.x; acc.y = bb.y;

#pragma unroll 1
    for (int h = 0; h < HH; h++) {
        const int z = b * HH + h;
        const size_t row = (size_t)z * NN + n;
        const int cnt = g_cnt[row];
        const float* Pz = g_p + (size_t)z * NN * 64;
        if (cnt == -1) {
            const float Pu = 1.0f / 2048.0f;
            float2 s = *(const float2*)(g_psum + z * 64 + dc);
            acc.x = fmaf(Pu, s.x, acc.x);
            acc.y = fmaf(Pu, s.y, acc.y);
        } else if (cnt >= 0) {
            const int*   si = g_si + row * MAXS;
            const float* sw = g_sw + row * MAXS;
            for (int j = 0; j < cnt; j++) {
                int   i0 = si[j];
                float w0 = sw[j];
                float2 v = *(const float2*)(Pz + (size_t)i0 * 64 + dc);
                acc.x = fmaf(w0, v.x, acc.x);
                acc.y = fmaf(w0, v.y, acc.y);
            }
        } else {
            const float* arow = att + row * NN;
            for (int c = 0; c < NN; c++) {
                float p = __ldcs(arow + c);
                if (p != 0.f) {
                    float2 v = *(const float2*)(Pz + (size_t)c * 64 + dc);
                    acc.x = fmaf(p, v.x, acc.x);
                    acc.y = fmaf(p, v.y, acc.y);
                }
            }
        }
    }
    *(float2*)(out + (size_t)gw * 64 + dc) = acc;
}

// ===========================================================================
extern "C" void kernel_launch(void* const* d_in, const int* in_sizes, int n_in,
                              void* d_out, int out_size)
{
    const float* x   = (const float*)d_in[0];
    const unsigned char* mask_raw = (const unsigned char*)d_in[1];
    const float* Wq  = (const float*)d_in[2];
    const float* Wk  = (const float*)d_in[3];
    const float* Wv  = (const float*)d_in[4];
    const float* Wo  = (const float*)d_in[5];
    const float* bo  = (const float*)d_in[6];

    float* out = (float*)d_out;
    float* pre = out + OUT_ELEMS;
    float* att = pre + PRE_ELEMS;

    static int smem_set = 0;
    if (!smem_set) {
        cudaFuncSetAttribute(dots_gemm,
                             cudaFuncAttributeMaxDynamicSharedMemorySize, DOTS_SMEM);
        cudaFuncSetAttribute(proj_mma,
                             cudaFuncAttributeMaxDynamicSharedMemorySize, PROJ_SMEM);
        cudaFuncSetAttribute(pvw_mma,
                             cudaFuncAttributeMaxDynamicSharedMemorySize, PVW_SMEM);
        smem_set = 1;
    }

    prep_compact_kernel<<<1, 256>>>(mask_raw);

    conv_all_kernel<<<1088, 256>>>(x, Wq, Wk, Wv, Wo);

    proj_mma<<<dim3(96, 32), 256, PROJ_SMEM>>>();

    pvw_mma<<<dim3(16, 16), 256, PVW_SMEM>>>();
    psum_part_kernel<<<dim3(16, 8), 256>>>();
    psum_red_kernel<<<4, 256>>>();

    dots_gemm<<<dim3(16, 16, 16), 256, DOTS_SMEM>>>(pre);

    entmax_kernel<<<BB * HH * NN / 8, 256>>>(pre, att);

    af_kernel<<<BB * NN / 8, 256>>>(att, bo, out);
}

// round 15
// speedup vs baseline: 1.0865x; 1.0865x over previous
#include <cuda_runtime.h>
#include <cuda_bf16.h>
#include <cuda_fp16.h>
#include <cstdint>

// Problem constants
#define BB 2
#define NN 2048
#define DIMX 64
#define HH 8
#define DD 512            // per-head dim
#define INNER 4096
#define SCALE 0.125f
#define MASKV -1e9f

#define OUT_ELEMS   (BB*NN*DIMX)          // 262144
#define PRE_ELEMS   (BB*HH*NN*NN)         // 67108864

#define NROWS (BB*HH*NN)   // 32768
#define NZ    (BB*HH)      // 16
#define MAXS  512

// Scratch
__device__ __half g_qh[BB*HH*NN*DD];
__device__ __half g_ql[BB*HH*NN*DD];
__device__ __half g_kh[BB*HH*NN*DD];
__device__ __half g_vh[BB*HH*NN*DD];
__device__ __half g_vl[BB*HH*NN*DD];
__device__ __half g_xh[4096*64];
__device__ __half g_xl[4096*64];
__device__ __half g_wh[12288*64];
__device__ __half g_wl[12288*64];
__device__ __half g_wo[HH*64*DD];
__device__ float  g_p[(size_t)NZ * NN * 64];
__device__ float  g_psum[NZ * 64];
__device__ float  g_psumP[NZ][8][64];
__device__ int    g_mask[BB*NN];
__device__ int    g_slot[BB*NN];         // n -> compact slot (-1 if masked)
__device__ int    g_rowmap[BB][NN];      // compact slot -> n (valid rows)
__device__ int    g_maskedmap[BB][NN];   // masked slot -> n (masked rows)
__device__ int    g_validcnt[BB];
__device__ int    g_si[(size_t)NROWS * MAXS];
__device__ float  g_sw[(size_t)NROWS * MAXS];
__device__ int    g_cnt[NROWS];

// ===========================================================================
// Helpers
// ===========================================================================
__device__ __forceinline__ uint32_t smem_u32(const void* p) {
    uint32_t r;
    asm("{ .reg .u64 t; cvta.to.shared.u64 t, %1; cvt.u32.u64 %0, t; }" : "=r"(r) : "l"(p));
    return r;
}
__device__ __forceinline__ void ldsm_x4(uint32_t* r, uint32_t addr) {
    asm volatile("ldmatrix.sync.aligned.m8n8.x4.shared.b16 {%0,%1,%2,%3}, [%4];"
        : "=r"(r[0]), "=r"(r[1]), "=r"(r[2]), "=r"(r[3]) : "r"(addr));
}
__device__ __forceinline__ void mma_f16(float* c, const uint32_t* a, const uint32_t* b) {
    asm volatile("mma.sync.aligned.m16n8k16.row.col.f32.f16.f16.f32 "
        "{%0,%1,%2,%3}, {%4,%5,%6,%7}, {%8,%9}, {%0,%1,%2,%3};"
        : "+f"(c[0]), "+f"(c[1]), "+f"(c[2]), "+f"(c[3])
        : "r"(a[0]), "r"(a[1]), "r"(a[2]), "r"(a[3]), "r"(b[0]), "r"(b[1]));
}
#define CP16(saddr, gptr) \
    asm volatile("cp.async.cg.shared.global [%0], [%1], 16;" :: "r"(saddr), "l"(gptr))
#define CP_COMMIT() asm volatile("cp.async.commit_group;")
#define CP_WAIT2()  asm volatile("cp.async.wait_group 2;")
#define CP_WAIT1()  asm volatile("cp.async.wait_group 1;")
#define CP_WAIT0()  asm volatile("cp.async.wait_group 0;")

__device__ __forceinline__ uint32_t swz(uint32_t r, uint32_t kb) {
    uint32_t off = r * 64u + kb;
    return off ^ ((off >> 3) & 0x70u);
}
__device__ __forceinline__ void split4h(float4 v, uint2& hh, uint2& ll) {
    __half2 h01 = __floats2half2_rn(v.x, v.y);
    __half2 h23 = __floats2half2_rn(v.z, v.w);
    float2 f01 = __half22float2(h01);
    float2 f23 = __half22float2(h23);
    __half2 l01 = __floats2half2_rn(v.x - f01.x, v.y - f01.y);
    __half2 l23 = __floats2half2_rn(v.z - f23.x, v.w - f23.y);
    hh.x = *(uint32_t*)&h01; hh.y = *(uint32_t*)&h23;
    ll.x = *(uint32_t*)&l01; ll.y = *(uint32_t*)&l23;
}

// ===========================================================================
// prep_mask + compact merged (single block)
// ===========================================================================
__global__ __launch_bounds__(256) void prep_compact_kernel(const unsigned char* __restrict__ raw) {
    __shared__ int cnt_f32, cnt_gt1;
    __shared__ int ps[256];
    if (threadIdx.x == 0) { cnt_f32 = 0; cnt_gt1 = 0; }
    __syncthreads();
    const unsigned int* u = (const unsigned int*)raw;
    int lf = 0, lg = 0;
    for (int i = threadIdx.x; i < 1024; i += blockDim.x) {
        unsigned int v = u[i];
        if (v == 0x3f800000u) lf++;
        else if (v > 1u) lg++;
    }
    atomicAdd(&cnt_f32, lf);
    atomicAdd(&cnt_gt1, lg);
    __syncthreads();
    int mode;
    if (cnt_f32 > 64) mode = 2;
    else if (cnt_gt1 > 64) mode = 1;
    else mode = 0;
    for (int i = threadIdx.x; i < BB*NN; i += blockDim.x) {
        int m;
        if (mode == 2)      m = (((const unsigned int*)raw)[i] != 0u) ? 1 : 0;
        else if (mode == 1) m = raw[i] ? 1 : 0;
        else                m = (((const int*)raw)[i] != 0) ? 1 : 0;
        g_mask[i] = m;
    }
    __syncthreads();

    for (int b = 0; b < BB; b++) {
        const int base_n = threadIdx.x * 8;
        int m[8], s = 0;
#pragma unroll
        for (int i = 0; i < 8; i++) { m[i] = g_mask[b * NN + base_n + i]; s += m[i]; }
        ps[threadIdx.x] = s;
        __syncthreads();
        for (int off = 1; off < 256; off <<= 1) {
            int v = ps[threadIdx.x];
            int u2 = (threadIdx.x >= off) ? ps[threadIdx.x - off] : 0;
            __syncthreads();
            ps[threadIdx.x] = v + u2;
            __syncthreads();
        }
        int pos = threadIdx.x ? ps[threadIdx.x - 1] : 0;
#pragma unroll
        for (int i = 0; i < 8; i++) {
            int n = base_n + i;
            if (m[i]) {
                g_rowmap[b][pos] = n;
                g_slot[b * NN + n] = pos;
                pos++;
            } else {
                g_maskedmap[b][n - pos] = n;
                g_slot[b * NN + n] = -1;
            }
        }
        if (threadIdx.x == 255) g_validcnt[b] = ps[255];
        __syncthreads();
    }
}

// ===========================================================================
// conv_all: fused conv_x (blocks 0..255), conv_w (256..1023), conv_wo (1024..1087)
// ===========================================================================
__global__ __launch_bounds__(256) void conv_all_kernel(
    const float* __restrict__ X,
    const float* __restrict__ Wq, const float* __restrict__ Wk, const float* __restrict__ Wv,
    const float* __restrict__ Wo)
{
    __shared__ float sh[64 * 65];
    const int bx = blockIdx.x;
    if (bx < 256) {
        int idx = bx * 256 + threadIdx.x;
        int m = idx >> 4;
        int k = (idx & 15) * 4;
        float4 v = ((const float4*)X)[idx];
        uint2 hh, ll;
        split4h(v, hh, ll);
        size_t tb = ((size_t)(m >> 7) * 2 + (k >> 5)) * 8192;
        uint32_t so = swz((uint32_t)(m & 127), (uint32_t)(k & 31) * 2);
        *(uint2*)((char*)g_xh + tb + so) = hh;
        *(uint2*)((char*)g_xl + tb + so) = ll;
    } else if (bx < 1024) {
        float (*t)[33] = (float(*)[33])sh;
        const int i = bx - 256;
        const int kt = i / 384;
        const int n0 = (i % 384) * 32;
        const float* W = (n0 < 4096) ? Wq : (n0 < 8192) ? Wk : Wv;
        const int nl0 = n0 & 4095;
        const int tx = threadIdx.x & 31, ty8 = threadIdx.x >> 5;
#pragma unroll
        for (int j = 0; j < 4; j++) {
            int kk = ty8 + j * 8;
            t[kk][tx] = W[(size_t)(kt * 32 + kk) * 4096 + nl0 + tx];
        }
        __syncthreads();
        const int nn = threadIdx.x >> 3;
        const int k4 = (threadIdx.x & 7) * 4;
        float4 v = make_float4(t[k4][nn], t[k4+1][nn], t[k4+2][nn], t[k4+3][nn]);
        uint2 hh, ll;
        split4h(v, hh, ll);
        const int gn = n0 + nn;
        const int gk = kt * 32 + k4;
        size_t tb = ((size_t)(gn >> 7) * 2 + (gk >> 5)) * 8192;
        uint32_t so = swz((uint32_t)(gn & 127), (uint32_t)(gk & 31) * 2);
        *(uint2*)((char*)g_wh + tb + so) = hh;
        *(uint2*)((char*)g_wl + tb + so) = ll;
    } else {
        float (*t)[65] = (float(*)[65])sh;
        const int i = bx - 1024;
        const int h = i >> 3;
        const int d0 = (i & 7) * 64;
#pragma unroll
        for (int j = 0; j < 16; j++) {
            int idx = threadIdx.x + j * 256;
            int dl = idx >> 6, dc = idx & 63;
            t[dl][dc] = Wo[(size_t)(h * 512 + d0 + dl) * 64 + dc];
        }
        __syncthreads();
#pragma unroll
        for (int j = 0; j < 4; j++) {
            int jj = threadIdx.x + j * 256;
            int dc = jj >> 4;
            int d4 = (jj & 15) * 4;
            __half2 h01 = __floats2half2_rn(t[d4+0][dc], t[d4+1][dc]);
            __half2 h23 = __floats2half2_rn(t[d4+2][dc], t[d4+3][dc]);
            uint2 hv;
            hv.x = *(uint32_t*)&h01; hv.y = *(uint32_t*)&h23;
            const int d = d0 + d4;
            size_t tb = ((size_t)h * 16 + (d >> 5)) * 4096;
            uint32_t so = swz((uint32_t)dc, (uint32_t)(d & 31) * 2);
            *(uint2*)((char*)g_wo + tb + so) = hv;
        }
    }
}

// ===========================================================================
// proj_mma: C = x @ [Wq|Wk|Wv], 3-term fp16 split, 2-chunk pipelined.
// Epilogue: SMEM repack -> uint4 stores. Q rows at compact slot.
// ===========================================================================
#define PROJ_SMEM 67584

__global__ __launch_bounds__(256, 2) void proj_mma()
{
    extern __shared__ char sm[];
    const uint32_t sbase = smem_u32(sm);
    const int tid = threadIdx.x;
    const int wid = tid >> 5, lane = tid & 31;
    const int wm = wid >> 2, wn = wid & 3;
    const int row0 = blockIdx.y * 128;
    const int col0 = blockIdx.x * 128;

    const char* xhB = (const char*)g_xh + (size_t)(blockIdx.y * 2) * 8192;
    const char* xlB = (const char*)g_xl + (size_t)(blockIdx.y * 2) * 8192;
    const char* whB = (const char*)g_wh + (size_t)(blockIdx.x * 2) * 8192;
    const char* wlB = (const char*)g_wl + (size_t)(blockIdx.x * 2) * 8192;

    auto issue = [&](int chk) {
        const uint32_t co = (uint32_t)chk * 8192;
#pragma unroll
        for (int k = 0; k < 2; k++) {
            uint32_t off = (uint32_t)(tid + k * 256) * 16;
            CP16(sbase + co + off,          xhB + co + off);
            CP16(sbase + 16384 + co + off,  xlB + co + off);
            CP16(sbase + 32768 + co + off,  whB + co + off);
            CP16(sbase + 49152 + co + off,  wlB + co + off);
        }
    };
    issue(0); CP_COMMIT();
    issue(1); CP_COMMIT();

    float acc[4][4][4];
#pragma unroll
    for (int mf = 0; mf < 4; mf++)
#pragma unroll
        for (int nf = 0; nf < 4; nf++)
#pragma unroll
            for (int r = 0; r < 4; r++) acc[mf][nf][r] = 0.f;

    const uint32_t a_row = (uint32_t)(wm * 64) + (lane & 15);
    const uint32_t a_kb  = ((lane >> 4) & 1) * 16;
    const uint32_t b_row = (uint32_t)(wn * 32) + ((lane >> 4) & 1) * 8 + (lane & 7);
    const uint32_t b_kb  = ((lane >> 3) & 1) * 16;

#pragma unroll
    for (int chk = 0; chk < 2; chk++) {
        if (chk == 0) CP_WAIT1(); else CP_WAIT0();
        __syncthreads();
        const uint32_t AH = sbase + (uint32_t)chk * 8192;
        const uint32_t AL = AH + 16384;
        const uint32_t BH = sbase + 32768 + (uint32_t)chk * 8192;
        const uint32_t BL = BH + 16384;
#pragma unroll
        for (int ks = 0; ks < 2; ks++) {
            const uint32_t kb0 = (uint32_t)ks * 32;
            uint32_t bh[4][2], bl[4][2];
#pragma unroll
            for (int p = 0; p < 2; p++) {
                uint32_t o = swz(b_row + p * 16, kb0 + b_kb);
                uint32_t t4[4];
                ldsm_x4(t4, BH + o);
                bh[2*p][0] = t4[0]; bh[2*p][1] = t4[1];
                bh[2*p+1][0] = t4[2]; bh[2*p+1][1] = t4[3];
                ldsm_x4(t4, BL + o);
                bl[2*p][0] = t4[0]; bl[2*p][1] = t4[1];
                bl[2*p+1][0] = t4[2]; bl[2*p+1][1] = t4[3];
            }
#pragma unroll
            for (int mf = 0; mf < 4; mf++) {
                uint32_t o = swz(a_row + mf * 16, kb0 + a_kb);
                uint32_t ah[4], al[4];
                ldsm_x4(ah, AH + o);
                ldsm_x4(al, AL + o);
#pragma unroll
                for (int nf = 0; nf < 4; nf++) {
                    mma_f16(acc[mf][nf], ah, bh[nf]);
                    mma_f16(acc[mf][nf], ah, bl[nf]);
                    mma_f16(acc[mf][nf], al, bh[nf]);
                }
            }
        }
    }

    // repack through SMEM
    __syncthreads();
    float* sacc = (float*)sm;   // [128][132]
    {
        const int rb = wm * 64 + (lane >> 2);
        const int cb = wn * 32 + (lane & 3) * 2;
#pragma unroll
        for (int mf = 0; mf < 4; mf++)
#pragma unroll
            for (int nf = 0; nf < 4; nf++)
#pragma unroll
                for (int rr = 0; rr < 2; rr++) {
                    int r = rb + mf * 16 + rr * 8;
                    int c = cb + nf * 8;
                    *(float2*)(sacc + r * 132 + c) =
                        make_float2(acc[mf][nf][rr*2+0], acc[mf][nf][rr*2+1]);
                }
    }
    __syncthreads();

    const int wsel = col0 >> 12;           // 0=Q 1=K 2=V
    const int dcol0 = col0 & 4095;
    const int r = tid >> 1;
    const int cH = (tid & 1) * 64;
    const int m = row0 + r;
    const int b = m >> 11, n = m & 2047;
    int nrow = n;
    if (wsel == 0) nrow = g_slot[b * NN + n];
    if (wsel != 0 || nrow >= 0) {
        const float* rowp = sacc + r * 132 + cH;
#pragma unroll
        for (int g = 0; g < 8; g++) {
            const int cg = cH + g * 8;
            const int col = dcol0 + cg;
            const int h = col >> 9, dd = col & 511;
            float4 e0 = *(const float4*)(rowp + g * 8);
            float4 e1 = *(const float4*)(rowp + g * 8 + 4);
            __half2 h0 = __floats2half2_rn(e0.x, e0.y);
            __half2 h1 = __floats2half2_rn(e0.z, e0.w);
            __half2 h2 = __floats2half2_rn(e1.x, e1.y);
            __half2 h3 = __floats2half2_rn(e1.z, e1.w);
            uint4 hv = make_uint4(*(uint32_t*)&h0, *(uint32_t*)&h1,
                                  *(uint32_t*)&h2, *(uint32_t*)&h3);
            size_t tb = (((size_t)(b*HH+h) * 16 + (nrow >> 7)) * 16 + (dd >> 5)) * 8192;
            uint32_t so = swz((uint32_t)(nrow & 127), (uint32_t)(dd & 31) * 2);
            if (wsel == 1) {
                *(uint4*)((char*)g_kh + tb + so) = hv;
            } else {
                float2 f0 = __half22float2(h0), f1 = __half22float2(h1);
                float2 f2 = __half22float2(h2), f3 = __half22float2(h3);
                __half2 l0 = __floats2half2_rn(e0.x - f0.x, e0.y - f0.y);
                __half2 l1 = __floats2half2_rn(e0.z - f1.x, e0.w - f1.y);
                __half2 l2 = __floats2half2_rn(e1.x - f2.x, e1.y - f2.y);
                __half2 l3 = __floats2half2_rn(e1.z - f3.x, e1.w - f3.y);
                uint4 lv = make_uint4(*(uint32_t*)&l0, *(uint32_t*)&l1,
                                      *(uint32_t*)&l2, *(uint32_t*)&l3);
                if (wsel == 0) {
                    *(uint4*)((char*)g_qh + tb + so) = hv;
                    *(uint4*)((char*)g_ql + tb + so) = lv;
                } else {
                    *(uint4*)((char*)g_vh + tb + so) = hv;
                    *(uint4*)((char*)g_vl + tb + so) = lv;
                }
            }
        }
    }
}

// ===========================================================================
// pvw_mma: P[z] = (Vh+Vl) @ Woh^T
// ===========================================================================
#define PVW_STAGE 20480u
#define PVW_SMEM (2 * 20480)

__global__ __launch_bounds__(256, 2) void pvw_mma()
{
    extern __shared__ char sm[];
    const uint32_t sbase = smem_u32(sm);
    const int tid = threadIdx.x;
    const int wid = tid >> 5, lane = tid & 31;
    const int wm = wid >> 1, wn = wid & 1;
    const int z = blockIdx.y, h = z & 7;
    const int nt = blockIdx.x;

    const char* vhB = (const char*)g_vh + (((size_t)z * 16 + nt) * 16) * 8192;
    const char* vlB = (const char*)g_vl + (((size_t)z * 16 + nt) * 16) * 8192;
    const char* woB = (const char*)g_wo + (size_t)(h * 16) * 4096;

    float acc[2][4][4];
#pragma unroll
    for (int mf = 0; mf < 2; mf++)
#pragma unroll
        for (int nf = 0; nf < 4; nf++)
#pragma unroll
            for (int r = 0; r < 4; r++) acc[mf][nf][r] = 0.f;

    auto issue = [&](int ch) {
        const uint32_t ss = sbase + (uint32_t)(ch & 1) * PVW_STAGE;
#pragma unroll
        for (int k = 0; k < 2; k++) {
            uint32_t off = (uint32_t)(tid + k * 256) * 16;
            CP16(ss + off,        vhB + (size_t)ch * 8192 + off);
            CP16(ss + 8192 + off, vlB + (size_t)ch * 8192 + off);
        }
        {
            uint32_t off = (uint32_t)tid * 16;
            CP16(ss + 16384 + off, woB + (size_t)ch * 4096 + off);
        }
    };

    issue(0); CP_COMMIT();

    const uint32_t a_row = (uint32_t)(wm * 32) + (lane & 15);
    const uint32_t a_kb  = ((lane >> 4) & 1) * 16;
    const uint32_t b_row = (uint32_t)(wn * 32) + ((lane >> 4) & 1) * 8 + (lane & 7);
    const uint32_t b_kb  = ((lane >> 3) & 1) * 16;

    for (int ch = 0; ch < 16; ++ch) {
        if (ch + 1 < 16) { issue(ch + 1); CP_COMMIT(); CP_WAIT1(); }
        else CP_WAIT0();
        __syncthreads();
        const uint32_t S = sbase + (uint32_t)(ch & 1) * PVW_STAGE;
        const uint32_t AH = S, AL = S + 8192, BH = S + 16384;
#pragma unroll
        for (int ks = 0; ks < 2; ks++) {
            const uint32_t kb0 = (uint32_t)ks * 32;
            uint32_t bh[4][2];
#pragma unroll
            for (int p = 0; p < 2; p++) {
                uint32_t o = swz(b_row + p * 16, kb0 + b_kb);
                uint32_t t4[4];
                ldsm_x4(t4, BH + o);
                bh[2*p][0] = t4[0]; bh[2*p][1] = t4[1];
                bh[2*p+1][0] = t4[2]; bh[2*p+1][1] = t4[3];
            }
#pragma unroll
            for (int mf = 0; mf < 2; mf++) {
                uint32_t o = swz(a_row + mf * 16, kb0 + a_kb);
                uint32_t ah[4], al[4];
                ldsm_x4(ah, AH + o);
                ldsm_x4(al, AL + o);
#pragma unroll
                for (int nf = 0; nf < 4; nf++) {
                    mma_f16(acc[mf][nf], ah, bh[nf]);
                    mma_f16(acc[mf][nf], al, bh[nf]);
                }
            }
        }
        __syncthreads();
    }

    const int r_lo = nt * 128 + wm * 32 + (lane >> 2);
    const int c_base = wn * 32 + (lane & 3) * 2;
    float* Pz = g_p + (size_t)z * NN * 64;
#pragma unroll
    for (int mf = 0; mf < 2; mf++) {
        int rg0 = r_lo + mf * 16;
#pragma unroll
        for (int nf = 0; nf < 4; nf++) {
            int cg = c_base + nf * 8;
            *(float2*)(Pz + (size_t)rg0 * 64 + cg)       = make_float2(acc[mf][nf][0], acc[mf][nf][1]);
            *(float2*)(Pz + (size_t)(rg0 + 8) * 64 + cg) = make_float2(acc[mf][nf][2], acc[mf][nf][3]);
        }
    }
}

// ===========================================================================
// psum: 2-phase parallel reduction
// ===========================================================================
__global__ __launch_bounds__(256) void psum_part_kernel()
{
    __shared__ float red[4][64];
    const int z = blockIdx.x, seg = blockIdx.y;
    const int d = threadIdx.x & 63, sub = threadIdx.x >> 6;
    const float* p = g_p + ((size_t)z * NN + seg * 256 + sub * 64) * 64 + d;
    float s = 0.f;
#pragma unroll 8
    for (int n = 0; n < 64; n++) s += p[(size_t)n * 64];
    red[sub][d] = s;
    __syncthreads();
    if (threadIdx.x < 64)
        g_psumP[z][seg][d] = red[0][d] + red[1][d] + red[2][d] + red[3][d];
}
__global__ __launch_bounds__(256) void psum_red_kernel()
{
    const int i = blockIdx.x * 256 + threadIdx.x;
    const int z = i >> 6, d = i & 63;
    float s = 0.f;
#pragma unroll
    for (int g = 0; g < 8; g++) s += g_psumP[z][g][d];
    g_psum[z * 64 + d] = s;
}

// ===========================================================================
// dots = scale*(Qh+Ql)@Kh^T (+col mask) on COMPACTED rows -> pre.
// Valid tiles: register-direct fragment stores (round-13 path, fastest).
// Pure-fill tiles (row0 >= cnt): coalesced float4 MASKV rows.
// ===========================================================================
#define DSTAGE 24576u
#define DOTS_SMEM (4 * 24576)

__global__ __launch_bounds__(256, 2) void dots_gemm(float* __restrict__ Out)
{
    extern __shared__ char sm[];
    __shared__ int cmask[128];
    const uint32_t sbase = smem_u32(sm);

    const int tid = threadIdx.x;
    const int wid = tid >> 5, lane = tid & 31;
    const int wm = wid >> 2, wn = wid & 3;
    const int z = blockIdx.z, b = z >> 3;
    const int row0 = blockIdx.y * 128, col0 = blockIdx.x * 128;

    const int cnt = g_validcnt[b];
    float* outz = Out + (size_t)z * NN * NN;

    if (row0 >= cnt) {
        // pure fill tile: coalesced MASKV rows through maskedmap
        const int r = tid >> 1;
        const int cH = (tid & 1) * 64;
        const int orig = g_maskedmap[b][row0 + r - cnt];
        float* rowp = outz + (size_t)orig * NN + col0 + cH;
        const float4 mv = make_float4(MASKV, MASKV, MASKV, MASKV);
#pragma unroll
        for (int g = 0; g < 16; g++)
            __stcs((float4*)(rowp + g * 4), mv);
        return;
    }

    if (tid < 128) cmask[tid] = g_mask[b * NN + col0 + tid];

    const char* qhB = (const char*)g_qh + (((size_t)z * 16 + blockIdx.y) * 16) * 8192;
    const char* qlB = (const char*)g_ql + (((size_t)z * 16 + blockIdx.y) * 16) * 8192;
    const char* khB = (const char*)g_kh + (((size_t)z * 16 + blockIdx.x) * 16) * 8192;

    float acc[4][4][4];
#pragma unroll
    for (int mf = 0; mf < 4; mf++)
#pragma unroll
        for (int nf = 0; nf < 4; nf++)
#pragma unroll
            for (int r = 0; r < 4; r++) acc[mf][nf][r] = 0.f;

    auto issue = [&](int ch) {
        const uint32_t ss = sbase + (uint32_t)(ch & 3) * DSTAGE;
        const char* q1 = qhB + (size_t)ch * 8192;
        const char* l1 = qlB + (size_t)ch * 8192;
        const char* k1 = khB + (size_t)ch * 8192;
#pragma unroll
        for (int k = 0; k < 2; k++) {
            uint32_t off = (uint32_t)(tid + k * 256) * 16;
            CP16(ss + off,         q1 + off);
            CP16(ss + 8192 + off,  l1 + off);
            CP16(ss + 16384 + off, k1 + off);
        }
    };

    issue(0); CP_COMMIT();
    issue(1); CP_COMMIT();
    issue(2); CP_COMMIT();

    const uint32_t a_row = (uint32_t)(wm * 64) + (lane & 15);
    const uint32_t a_kb  = ((lane >> 4) & 1) * 16;
    const uint32_t b_row = (uint32_t)(wn * 32) + ((lane >> 4) & 1) * 8 + (lane & 7);
    const uint32_t b_kb  = ((lane >> 3) & 1) * 16;

    for (int ch = 0; ch < 16; ++ch) {
        CP_WAIT2();
        __syncthreads();
        const uint32_t S = sbase + (uint32_t)(ch & 3) * DSTAGE;
        const uint32_t AH = S, AL = S + 8192, BH = S + 16384;
#pragma unroll
        for (int ks = 0; ks < 2; ks++) {
            const uint32_t kb0 = (uint32_t)ks * 32;
            uint32_t bh[4][2];
#pragma unroll
            for (int p = 0; p < 2; p++) {
                uint32_t o = swz(b_row + p * 16, kb0 + b_kb);
                uint32_t t4[4];
                ldsm_x4(t4, BH + o);
                bh[2*p][0] = t4[0]; bh[2*p][1] = t4[1];
                bh[2*p+1][0] = t4[2]; bh[2*p+1][1] = t4[3];
            }
#pragma unroll
            for (int mf = 0; mf < 4; mf++) {
                uint32_t o = swz(a_row + mf * 16, kb0 + a_kb);
                uint32_t ah[4], al[4];
                ldsm_x4(ah, AH + o);
                ldsm_x4(al, AL + o);
#pragma unroll
                for (int nf = 0; nf < 4; nf++) {
                    mma_f16(acc[mf][nf], ah, bh[nf]);
                    mma_f16(acc[mf][nf], al, bh[nf]);
                }
            }
        }
        if (ch + 3 < 16) issue(ch + 3);
        CP_COMMIT();
    }

    // epilogue: register-direct fragment stores (valid rows + rare tail fills)
    const int r_lo = row0 + wm * 64 + (lane >> 2);
    const int c_base = wn * 32 + (lane & 3) * 2;
#pragma unroll
    for (int mf = 0; mf < 4; mf++) {
#pragma unroll
        for (int rr = 0; rr < 2; rr++) {
            const int cr = r_lo + mf * 16 + rr * 8;
            if (cr < cnt) {
                const int orig = g_rowmap[b][cr];
                float* rowp = outz + (size_t)orig * NN + col0;
#pragma unroll
                for (int nf = 0; nf < 4; nf++) {
                    int cg = c_base + nf * 8;
                    float2 v;
                    v.x = cmask[cg]     ? acc[mf][nf][rr*2+0] * SCALE : MASKV;
                    v.y = cmask[cg + 1] ? acc[mf][nf][rr*2+1] * SCALE : MASKV;
                    __stcs((float2*)(rowp + cg), v);
                }
            } else {
                const int orig = g_maskedmap[b][cr - cnt];
                float* rowp = outz + (size_t)orig * NN + col0;
                const float2 mv = make_float2(MASKV, MASKV);
#pragma unroll
                for (int nf = 0; nf < 4; nf++)
                    __stcs((float2*)(rowp + c_base + nf * 8), mv);
            }
        }
    }
}

// ===========================================================================
// entmax-1.5: streaming loads/stores; Newton with uniform early-exit
// ===========================================================================
__global__ __launch_bounds__(256) void entmax_kernel(
    const float* __restrict__ pre, float* __restrict__ att)
{
    const int wid = threadIdx.x >> 5, lane = threadIdx.x & 31;
    const size_t row = (size_t)blockIdx.x * 8 + wid;
    const int z = (int)(row >> 11), n = (int)(row & 2047), b = z >> 3;
    float4* o4 = (float4*)(att + row * NN);

    if (!g_mask[b * NN + n]) {
        const float P = 1.0f / 2048.0f;
        float4 u = make_float4(P, P, P, P);
#pragma unroll
        for (int i = 0; i < 16; i++) __stcs(&o4[lane + i * 32], u);
        if (lane == 0) g_cnt[row] = -1;
        return;
    }

    const float4* p4 = (const float4*)(pre + row * NN);
    float x[64];
    float mx = -3.0e38f;
#pragma unroll
    for (int i = 0; i < 16; i++) {
        float4 v = __ldcs(&p4[lane + i * 32]);
        x[4*i+0] = 0.5f * v.x; x[4*i+1] = 0.5f * v.y;
        x[4*i+2] = 0.5f * v.z; x[4*i+3] = 0.5f * v.w;
        mx = fmaxf(mx, fmaxf(fmaxf(x[4*i], x[4*i+1]), fmaxf(x[4*i+2], x[4*i+3])));
    }
#pragma unroll
    for (int off = 16; off; off >>= 1)
        mx = fmaxf(mx, __shfl_xor_sync(0xffffffffu, mx, off));
#pragma unroll
    for (int j = 0; j < 64; j++) x[j] -= mx;

    float tau = -1.0f;
#pragma unroll 1
    for (int it = 0; it < 12; ++it) {
        float s1 = 0.f, s2 = 0.f;
#pragma unroll
        for (int j = 0; j < 64; j++) {
            float d = fmaxf(x[j] - tau, 0.f);
            s1 += d;
            s2 = fmaf(d, d, s2);
        }
#pragma unroll
        for (int off = 16; off; off >>= 1) {
            s1 += __shfl_xor_sync(0xffffffffu, s1, off);
            s2 += __shfl_xor_sync(0xffffffffu, s2, off);
        }
        float step = (s1 > 1e-20f) ? (s2 - 1.0f) / (2.0f * s1) : 0.f;
        tau += step;
        if (fabsf(step) < 1e-6f) break;
    }

#pragma unroll
    for (int i = 0; i < 16; i++) {
        float4 w;
        float d;
        d = fmaxf(x[4*i+0] - tau, 0.f); w.x = d * d;
        d = fmaxf(x[4*i+1] - tau, 0.f); w.y = d * d;
        d = fmaxf(x[4*i+2] - tau, 0.f); w.z = d * d;
        d = fmaxf(x[4*i+3] - tau, 0.f); w.w = d * d;
        __stcs(&o4[lane + i * 32], w);
    }

    int cl = 0;
#pragma unroll
    for (int j = 0; j < 64; j++) cl += (x[j] > tau) ? 1 : 0;
    int v = cl;
#pragma unroll
    for (int d = 1; d < 32; d <<= 1) {
        int t = __shfl_up_sync(0xffffffffu, v, d);
        if (lane >= d) v += t;
    }
    int total = __shfl_sync(0xffffffffu, v, 31);
    int pos = v - cl;
    if (total <= MAXS) {
        int*   si = g_si + row * MAXS;
        float* sw = g_sw + row * MAXS;
#pragma unroll
        for (int i = 0; i < 16; i++)
#pragma unroll
            for (int c = 0; c < 4; c++) {
                int j = 4*i + c;
                if (x[j] > tau) {
                    float d = x[j] - tau;
                    si[pos] = 4*lane + 128*i + c;
                    sw[pos] = d * d;
                    pos++;
                }
            }
        if (lane == 31) g_cnt[row] = total;
    } else if (lane == 31) {
        g_cnt[row] = -2;
    }
}

// ===========================================================================
// Fused sparse attention-out
// ===========================================================================
__global__ __launch_bounds__(256) void af_kernel(
    const float* __restrict__ att, const float* __restrict__ bo, float* __restrict__ out)
{
    const int wid = threadIdx.x >> 5, lane = threadIdx.x & 31;
    const int gw = blockIdx.x * 8 + wid;
    const int b = gw >> 11, n = gw & 2047;
    const int dc = lane * 2;

    float2 acc;
    float2 bb = *(const float2*)(bo + dc);
    acc.x = bb.x; acc.y = bb.y;

#pragma unroll 1
    for (int h = 0; h < HH; h++) {
        const int z = b * HH + h;
        const size_t row = (size_t)z * NN + n;
        const int cnt = g_cnt[row];
        const float* Pz = g_p + (size_t)z * NN * 64;
        if (cnt == -1) {
            const float Pu = 1.0f / 2048.0f;
            float2 s = *(const float2*)(g_psum + z * 64 + dc);
            acc.x = fmaf(Pu, s.x, acc.x);
            acc.y = fmaf(Pu, s.y, acc.y);
        } else if (cnt >= 0) {
            const int*   si = g_si + row * MAXS;
            const float* sw = g_sw + row * MAXS;
            for (int j = 0; j < cnt; j++) {
                int   i0 = si[j];
                float w0 = sw[j];
                float2 v = *(const float2*)(Pz + (size_t)i0 * 64 + dc);
                acc.x = fmaf(w0, v.x, acc.x);
                acc.y = fmaf(w0, v.y, acc.y);
            }
        } else {
            const float* arow = att + row * NN;
            for (int c = 0; c < NN; c++) {
                float p = __ldcs(arow + c);
                if (p != 0.f) {
                    float2 v = *(const float2*)(Pz + (size_t)c * 64 + dc);
                    acc.x = fmaf(p, v.x, acc.x);
                    acc.y = fmaf(p, v.y, acc.y);
                }
            }
        }
    }
    *(float2*)(out + (size_t)gw * 64 + dc) = acc;
}

// ===========================================================================
extern "C" void kernel_launch(void* const* d_in, const int* in_sizes, int n_in,
                              void* d_out, int out_size)
{
    const float* x   = (const float*)d_in[0];
    const unsigned char* mask_raw = (const unsigned char*)d_in[1];
    const float* Wq  = (const float*)d_in[2];
    const float* Wk  = (const float*)d_in[3];
    const float* Wv  = (const float*)d_in[4];
    const float* Wo  = (const float*)d_in[5];
    const float* bo  = (const float*)d_in[6];

    float* out = (float*)d_out;
    float* pre = out + OUT_ELEMS;
    float* att = pre + PRE_ELEMS;

    static int smem_set = 0;
    if (!smem_set) {
        cudaFuncSetAttribute(dots_gemm,
                             cudaFuncAttributeMaxDynamicSharedMemorySize, DOTS_SMEM);
        cudaFuncSetAttribute(proj_mma,
                             cudaFuncAttributeMaxDynamicSharedMemorySize, PROJ_SMEM);
        cudaFuncSetAttribute(pvw_mma,
                             cudaFuncAttributeMaxDynamicSharedMemorySize, PVW_SMEM);
        smem_set = 1;
    }

    prep_compact_kernel<<<1, 256>>>(mask_raw);

    conv_all_kernel<<<1088, 256>>>(x, Wq, Wk, Wv, Wo);

    proj_mma<<<dim3(96, 32), 256, PROJ_SMEM>>>();

    pvw_mma<<<dim3(16, 16), 256, PVW_SMEM>>>();
    psum_part_kernel<<<dim3(16, 8), 256>>>();
    psum_red_kernel<<<4, 256>>>();

    dots_gemm<<<dim3(16, 16, 16), 256, DOTS_SMEM>>>(pre);

    entmax_kernel<<<BB * HH * NN / 8, 256>>>(pre, att);

    af_kernel<<<BB * NN / 8, 256>>>(att, bo, out);
}

// round 16
// speedup vs baseline: 1.1267x; 1.0371x over previous
#include <cuda_runtime.h>
#include <cuda_bf16.h>
#include <cuda_fp16.h>
#include <cstdint>

// Problem constants
#define BB 2
#define NN 2048
#define DIMX 64
#define HH 8
#define DD 512            // per-head dim
#define INNER 4096
#define SCALE 0.125f
#define MASKV -1e9f

#define OUT_ELEMS   (BB*NN*DIMX)          // 262144
#define PRE_ELEMS   (BB*HH*NN*NN)         // 67108864

#define NROWS (BB*HH*NN)   // 32768
#define NZ    (BB*HH)      // 16
#define MAXS  512

// Scratch
__device__ __half g_qh[BB*HH*NN*DD];
__device__ __half g_ql[BB*HH*NN*DD];
__device__ __half g_kh[BB*HH*NN*DD];
__device__ __half g_vh[BB*HH*NN*DD];
__device__ __half g_vl[BB*HH*NN*DD];
__device__ __half g_xh[4096*64];
__device__ __half g_xl[4096*64];
__device__ __half g_wh[12288*64];
__device__ __half g_wl[12288*64];
__device__ __half g_wo[HH*64*DD];
__device__ float  g_p[(size_t)NZ * NN * 64];
__device__ float  g_psum[NZ * 64];
__device__ float  g_psumP[NZ][8][64];
__device__ int    g_mask[BB*NN];
__device__ int    g_slot[BB*NN];         // n -> compact slot (-1 if masked)
__device__ int    g_rowmap[BB][NN];      // compact slot -> n (valid rows)
__device__ int    g_maskedmap[BB][NN];   // masked slot -> n (masked rows)
__device__ int    g_validcnt[BB];
__device__ int    g_si[(size_t)NROWS * MAXS];
__device__ float  g_sw[(size_t)NROWS * MAXS];
__device__ int    g_cnt[NROWS];

// ===========================================================================
// Helpers
// ===========================================================================
__device__ __forceinline__ uint32_t smem_u32(const void* p) {
    uint32_t r;
    asm("{ .reg .u64 t; cvta.to.shared.u64 t, %1; cvt.u32.u64 %0, t; }" : "=r"(r) : "l"(p));
    return r;
}
__device__ __forceinline__ void ldsm_x4(uint32_t* r, uint32_t addr) {
    asm volatile("ldmatrix.sync.aligned.m8n8.x4.shared.b16 {%0,%1,%2,%3}, [%4];"
        : "=r"(r[0]), "=r"(r[1]), "=r"(r[2]), "=r"(r[3]) : "r"(addr));
}
__device__ __forceinline__ void mma_f16(float* c, const uint32_t* a, const uint32_t* b) {
    asm volatile("mma.sync.aligned.m16n8k16.row.col.f32.f16.f16.f32 "
        "{%0,%1,%2,%3}, {%4,%5,%6,%7}, {%8,%9}, {%0,%1,%2,%3};"
        : "+f"(c[0]), "+f"(c[1]), "+f"(c[2]), "+f"(c[3])
        : "r"(a[0]), "r"(a[1]), "r"(a[2]), "r"(a[3]), "r"(b[0]), "r"(b[1]));
}
#define CP16(saddr, gptr) \
    asm volatile("cp.async.cg.shared.global [%0], [%1], 16;" :: "r"(saddr), "l"(gptr))
#define CP_COMMIT() asm volatile("cp.async.commit_group;")
#define CP_WAIT2()  asm volatile("cp.async.wait_group 2;")
#define CP_WAIT1()  asm volatile("cp.async.wait_group 1;")
#define CP_WAIT0()  asm volatile("cp.async.wait_group 0;")

__device__ __forceinline__ uint32_t swz(uint32_t r, uint32_t kb) {
    uint32_t off = r * 64u + kb;
    return off ^ ((off >> 3) & 0x70u);
}
__device__ __forceinline__ void split4h(float4 v, uint2& hh, uint2& ll) {
    __half2 h01 = __floats2half2_rn(v.x, v.y);
    __half2 h23 = __floats2half2_rn(v.z, v.w);
    float2 f01 = __half22float2(h01);
    float2 f23 = __half22float2(h23);
    __half2 l01 = __floats2half2_rn(v.x - f01.x, v.y - f01.y);
    __half2 l23 = __floats2half2_rn(v.z - f23.x, v.w - f23.y);
    hh.x = *(uint32_t*)&h01; hh.y = *(uint32_t*)&h23;
    ll.x = *(uint32_t*)&l01; ll.y = *(uint32_t*)&l23;
}

// ===========================================================================
// prep_mask + compact merged (single block)
// ===========================================================================
__global__ __launch_bounds__(256) void prep_compact_kernel(const unsigned char* __restrict__ raw) {
    __shared__ int cnt_f32, cnt_gt1;
    __shared__ int ps[256];
    if (threadIdx.x == 0) { cnt_f32 = 0; cnt_gt1 = 0; }
    __syncthreads();
    const unsigned int* u = (const unsigned int*)raw;
    int lf = 0, lg = 0;
    for (int i = threadIdx.x; i < 1024; i += blockDim.x) {
        unsigned int v = u[i];
        if (v == 0x3f800000u) lf++;
        else if (v > 1u) lg++;
    }
    atomicAdd(&cnt_f32, lf);
    atomicAdd(&cnt_gt1, lg);
    __syncthreads();
    int mode;
    if (cnt_f32 > 64) mode = 2;
    else if (cnt_gt1 > 64) mode = 1;
    else mode = 0;
    for (int i = threadIdx.x; i < BB*NN; i += blockDim.x) {
        int m;
        if (mode == 2)      m = (((const unsigned int*)raw)[i] != 0u) ? 1 : 0;
        else if (mode == 1) m = raw[i] ? 1 : 0;
        else                m = (((const int*)raw)[i] != 0) ? 1 : 0;
        g_mask[i] = m;
    }
    __syncthreads();

    for (int b = 0; b < BB; b++) {
        const int base_n = threadIdx.x * 8;
        int m[8], s = 0;
#pragma unroll
        for (int i = 0; i < 8; i++) { m[i] = g_mask[b * NN + base_n + i]; s += m[i]; }
        ps[threadIdx.x] = s;
        __syncthreads();
        for (int off = 1; off < 256; off <<= 1) {
            int v = ps[threadIdx.x];
            int u2 = (threadIdx.x >= off) ? ps[threadIdx.x - off] : 0;
            __syncthreads();
            ps[threadIdx.x] = v + u2;
            __syncthreads();
        }
        int pos = threadIdx.x ? ps[threadIdx.x - 1] : 0;
#pragma unroll
        for (int i = 0; i < 8; i++) {
            int n = base_n + i;
            if (m[i]) {
                g_rowmap[b][pos] = n;
                g_slot[b * NN + n] = pos;
                pos++;
            } else {
                g_maskedmap[b][n - pos] = n;
                g_slot[b * NN + n] = -1;
            }
        }
        if (threadIdx.x == 255) g_validcnt[b] = ps[255];
        __syncthreads();
    }
}

// ===========================================================================
// conv_all: fused conv_x (blocks 0..255), conv_w (256..1023), conv_wo (1024..1087)
// ===========================================================================
__global__ __launch_bounds__(256) void conv_all_kernel(
    const float* __restrict__ X,
    const float* __restrict__ Wq, const float* __restrict__ Wk, const float* __restrict__ Wv,
    const float* __restrict__ Wo)
{
    __shared__ float sh[64 * 65];
    const int bx = blockIdx.x;
    if (bx < 256) {
        int idx = bx * 256 + threadIdx.x;
        int m = idx >> 4;
        int k = (idx & 15) * 4;
        float4 v = ((const float4*)X)[idx];
        uint2 hh, ll;
        split4h(v, hh, ll);
        size_t tb = ((size_t)(m >> 7) * 2 + (k >> 5)) * 8192;
        uint32_t so = swz((uint32_t)(m & 127), (uint32_t)(k & 31) * 2);
        *(uint2*)((char*)g_xh + tb + so) = hh;
        *(uint2*)((char*)g_xl + tb + so) = ll;
    } else if (bx < 1024) {
        float (*t)[33] = (float(*)[33])sh;
        const int i = bx - 256;
        const int kt = i / 384;
        const int n0 = (i % 384) * 32;
        const float* W = (n0 < 4096) ? Wq : (n0 < 8192) ? Wk : Wv;
        const int nl0 = n0 & 4095;
        const int tx = threadIdx.x & 31, ty8 = threadIdx.x >> 5;
#pragma unroll
        for (int j = 0; j < 4; j++) {
            int kk = ty8 + j * 8;
            t[kk][tx] = W[(size_t)(kt * 32 + kk) * 4096 + nl0 + tx];
        }
        __syncthreads();
        const int nn = threadIdx.x >> 3;
        const int k4 = (threadIdx.x & 7) * 4;
        float4 v = make_float4(t[k4][nn], t[k4+1][nn], t[k4+2][nn], t[k4+3][nn]);
        uint2 hh, ll;
        split4h(v, hh, ll);
        const int gn = n0 + nn;
        const int gk = kt * 32 + k4;
        size_t tb = ((size_t)(gn >> 7) * 2 + (gk >> 5)) * 8192;
        uint32_t so = swz((uint32_t)(gn & 127), (uint32_t)(gk & 31) * 2);
        *(uint2*)((char*)g_wh + tb + so) = hh;
        *(uint2*)((char*)g_wl + tb + so) = ll;
    } else {
        float (*t)[65] = (float(*)[65])sh;
        const int i = bx - 1024;
        const int h = i >> 3;
        const int d0 = (i & 7) * 64;
#pragma unroll
        for (int j = 0; j < 16; j++) {
            int idx = threadIdx.x + j * 256;
            int dl = idx >> 6, dc = idx & 63;
            t[dl][dc] = Wo[(size_t)(h * 512 + d0 + dl) * 64 + dc];
        }
        __syncthreads();
#pragma unroll
        for (int j = 0; j < 4; j++) {
            int jj = threadIdx.x + j * 256;
            int dc = jj >> 4;
            int d4 = (jj & 15) * 4;
            __half2 h01 = __floats2half2_rn(t[d4+0][dc], t[d4+1][dc]);
            __half2 h23 = __floats2half2_rn(t[d4+2][dc], t[d4+3][dc]);
            uint2 hv;
            hv.x = *(uint32_t*)&h01; hv.y = *(uint32_t*)&h23;
            const int d = d0 + d4;
            size_t tb = ((size_t)h * 16 + (d >> 5)) * 4096;
            uint32_t so = swz((uint32_t)dc, (uint32_t)(d & 31) * 2);
            *(uint2*)((char*)g_wo + tb + so) = hv;
        }
    }
}

// ===========================================================================
// proj_mma: C = x @ [Wq|Wk|Wv], 3-term fp16 split, 2-chunk pipelined.
// Epilogue: SMEM repack -> uint4 stores. Q rows at compact slot.
// ===========================================================================
#define PROJ_SMEM 67584

__global__ __launch_bounds__(256, 2) void proj_mma()
{
    extern __shared__ char sm[];
    const uint32_t sbase = smem_u32(sm);
    const int tid = threadIdx.x;
    const int wid = tid >> 5, lane = tid & 31;
    const int wm = wid >> 2, wn = wid & 3;
    const int row0 = blockIdx.y * 128;
    const int col0 = blockIdx.x * 128;

    const char* xhB = (const char*)g_xh + (size_t)(blockIdx.y * 2) * 8192;
    const char* xlB = (const char*)g_xl + (size_t)(blockIdx.y * 2) * 8192;
    const char* whB = (const char*)g_wh + (size_t)(blockIdx.x * 2) * 8192;
    const char* wlB = (const char*)g_wl + (size_t)(blockIdx.x * 2) * 8192;

    auto issue = [&](int chk) {
        const uint32_t co = (uint32_t)chk * 8192;
#pragma unroll
        for (int k = 0; k < 2; k++) {
            uint32_t off = (uint32_t)(tid + k * 256) * 16;
            CP16(sbase + co + off,          xhB + co + off);
            CP16(sbase + 16384 + co + off,  xlB + co + off);
            CP16(sbase + 32768 + co + off,  whB + co + off);
            CP16(sbase + 49152 + co + off,  wlB + co + off);
        }
    };
    issue(0); CP_COMMIT();
    issue(1); CP_COMMIT();

    float acc[4][4][4];
#pragma unroll
    for (int mf = 0; mf < 4; mf++)
#pragma unroll
        for (int nf = 0; nf < 4; nf++)
#pragma unroll
            for (int r = 0; r < 4; r++) acc[mf][nf][r] = 0.f;

    const uint32_t a_row = (uint32_t)(wm * 64) + (lane & 15);
    const uint32_t a_kb  = ((lane >> 4) & 1) * 16;
    const uint32_t b_row = (uint32_t)(wn * 32) + ((lane >> 4) & 1) * 8 + (lane & 7);
    const uint32_t b_kb  = ((lane >> 3) & 1) * 16;

#pragma unroll
    for (int chk = 0; chk < 2; chk++) {
        if (chk == 0) CP_WAIT1(); else CP_WAIT0();
        __syncthreads();
        const uint32_t AH = sbase + (uint32_t)chk * 8192;
        const uint32_t AL = AH + 16384;
        const uint32_t BH = sbase + 32768 + (uint32_t)chk * 8192;
        const uint32_t BL = BH + 16384;
#pragma unroll
        for (int ks = 0; ks < 2; ks++) {
            const uint32_t kb0 = (uint32_t)ks * 32;
            uint32_t bh[4][2], bl[4][2];
#pragma unroll
            for (int p = 0; p < 2; p++) {
                uint32_t o = swz(b_row + p * 16, kb0 + b_kb);
                uint32_t t4[4];
                ldsm_x4(t4, BH + o);
                bh[2*p][0] = t4[0]; bh[2*p][1] = t4[1];
                bh[2*p+1][0] = t4[2]; bh[2*p+1][1] = t4[3];
                ldsm_x4(t4, BL + o);
                bl[2*p][0] = t4[0]; bl[2*p][1] = t4[1];
                bl[2*p+1][0] = t4[2]; bl[2*p+1][1] = t4[3];
            }
#pragma unroll
            for (int mf = 0; mf < 4; mf++) {
                uint32_t o = swz(a_row + mf * 16, kb0 + a_kb);
                uint32_t ah[4], al[4];
                ldsm_x4(ah, AH + o);
                ldsm_x4(al, AL + o);
#pragma unroll
                for (int nf = 0; nf < 4; nf++) {
                    mma_f16(acc[mf][nf], ah, bh[nf]);
                    mma_f16(acc[mf][nf], ah, bl[nf]);
                    mma_f16(acc[mf][nf], al, bh[nf]);
                }
            }
        }
    }

    // repack through SMEM
    __syncthreads();
    float* sacc = (float*)sm;   // [128][132]
    {
        const int rb = wm * 64 + (lane >> 2);
        const int cb = wn * 32 + (lane & 3) * 2;
#pragma unroll
        for (int mf = 0; mf < 4; mf++)
#pragma unroll
            for (int nf = 0; nf < 4; nf++)
#pragma unroll
                for (int rr = 0; rr < 2; rr++) {
                    int r = rb + mf * 16 + rr * 8;
                    int c = cb + nf * 8;
                    *(float2*)(sacc + r * 132 + c) =
                        make_float2(acc[mf][nf][rr*2+0], acc[mf][nf][rr*2+1]);
                }
    }
    __syncthreads();

    const int wsel = col0 >> 12;           // 0=Q 1=K 2=V
    const int dcol0 = col0 & 4095;
    const int r = tid >> 1;
    const int cH = (tid & 1) * 64;
    const int m = row0 + r;
    const int b = m >> 11, n = m & 2047;
    int nrow = n;
    if (wsel == 0) nrow = g_slot[b * NN + n];
    if (wsel != 0 || nrow >= 0) {
        const float* rowp = sacc + r * 132 + cH;
#pragma unroll
        for (int g = 0; g < 8; g++) {
            const int cg = cH + g * 8;
            const int col = dcol0 + cg;
            const int h = col >> 9, dd = col & 511;
            float4 e0 = *(const float4*)(rowp + g * 8);
            float4 e1 = *(const float4*)(rowp + g * 8 + 4);
            __half2 h0 = __floats2half2_rn(e0.x, e0.y);
            __half2 h1 = __floats2half2_rn(e0.z, e0.w);
            __half2 h2 = __floats2half2_rn(e1.x, e1.y);
            __half2 h3 = __floats2half2_rn(e1.z, e1.w);
            uint4 hv = make_uint4(*(uint32_t*)&h0, *(uint32_t*)&h1,
                                  *(uint32_t*)&h2, *(uint32_t*)&h3);
            size_t tb = (((size_t)(b*HH+h) * 16 + (nrow >> 7)) * 16 + (dd >> 5)) * 8192;
            uint32_t so = swz((uint32_t)(nrow & 127), (uint32_t)(dd & 31) * 2);
            if (wsel == 1) {
                *(uint4*)((char*)g_kh + tb + so) = hv;
            } else {
                float2 f0 = __half22float2(h0), f1 = __half22float2(h1);
                float2 f2 = __half22float2(h2), f3 = __half22float2(h3);
                __half2 l0 = __floats2half2_rn(e0.x - f0.x, e0.y - f0.y);
                __half2 l1 = __floats2half2_rn(e0.z - f1.x, e0.w - f1.y);
                __half2 l2 = __floats2half2_rn(e1.x - f2.x, e1.y - f2.y);
                __half2 l3 = __floats2half2_rn(e1.z - f3.x, e1.w - f3.y);
                uint4 lv = make_uint4(*(uint32_t*)&l0, *(uint32_t*)&l1,
                                      *(uint32_t*)&l2, *(uint32_t*)&l3);
                if (wsel == 0) {
                    *(uint4*)((char*)g_qh + tb + so) = hv;
                    *(uint4*)((char*)g_ql + tb + so) = lv;
                } else {
                    *(uint4*)((char*)g_vh + tb + so) = hv;
                    *(uint4*)((char*)g_vl + tb + so) = lv;
                }
            }
        }
    }
}

// ===========================================================================
// pvw_mma: P[z] = (Vh+Vl) @ Woh^T
// ===========================================================================
#define PVW_STAGE 20480u
#define PVW_SMEM (2 * 20480)

__global__ __launch_bounds__(256, 2) void pvw_mma()
{
    extern __shared__ char sm[];
    const uint32_t sbase = smem_u32(sm);
    const int tid = threadIdx.x;
    const int wid = tid >> 5, lane = tid & 31;
    const int wm = wid >> 1, wn = wid & 1;
    const int z = blockIdx.y, h = z & 7;
    const int nt = blockIdx.x;

    const char* vhB = (const char*)g_vh + (((size_t)z * 16 + nt) * 16) * 8192;
    const char* vlB = (const char*)g_vl + (((size_t)z * 16 + nt) * 16) * 8192;
    const char* woB = (const char*)g_wo + (size_t)(h * 16) * 4096;

    float acc[2][4][4];
#pragma unroll
    for (int mf = 0; mf < 2; mf++)
#pragma unroll
        for (int nf = 0; nf < 4; nf++)
#pragma unroll
            for (int r = 0; r < 4; r++) acc[mf][nf][r] = 0.f;

    auto issue = [&](int ch) {
        const uint32_t ss = sbase + (uint32_t)(ch & 1) * PVW_STAGE;
#pragma unroll
        for (int k = 0; k < 2; k++) {
            uint32_t off = (uint32_t)(tid + k * 256) * 16;
            CP16(ss + off,        vhB + (size_t)ch * 8192 + off);
            CP16(ss + 8192 + off, vlB + (size_t)ch * 8192 + off);
        }
        {
            uint32_t off = (uint32_t)tid * 16;
            CP16(ss + 16384 + off, woB + (size_t)ch * 4096 + off);
        }
    };

    issue(0); CP_COMMIT();

    const uint32_t a_row = (uint32_t)(wm * 32) + (lane & 15);
    const uint32_t a_kb  = ((lane >> 4) & 1) * 16;
    const uint32_t b_row = (uint32_t)(wn * 32) + ((lane >> 4) & 1) * 8 + (lane & 7);
    const uint32_t b_kb  = ((lane >> 3) & 1) * 16;

    for (int ch = 0; ch < 16; ++ch) {
        if (ch + 1 < 16) { issue(ch + 1); CP_COMMIT(); CP_WAIT1(); }
        else CP_WAIT0();
        __syncthreads();
        const uint32_t S = sbase + (uint32_t)(ch & 1) * PVW_STAGE;
        const uint32_t AH = S, AL = S + 8192, BH = S + 16384;
#pragma unroll
        for (int ks = 0; ks < 2; ks++) {
            const uint32_t kb0 = (uint32_t)ks * 32;
            uint32_t bh[4][2];
#pragma unroll
            for (int p = 0; p < 2; p++) {
                uint32_t o = swz(b_row + p * 16, kb0 + b_kb);
                uint32_t t4[4];
                ldsm_x4(t4, BH + o);
                bh[2*p][0] = t4[0]; bh[2*p][1] = t4[1];
                bh[2*p+1][0] = t4[2]; bh[2*p+1][1] = t4[3];
            }
#pragma unroll
            for (int mf = 0; mf < 2; mf++) {
                uint32_t o = swz(a_row + mf * 16, kb0 + a_kb);
                uint32_t ah[4], al[4];
                ldsm_x4(ah, AH + o);
                ldsm_x4(al, AL + o);
#pragma unroll
                for (int nf = 0; nf < 4; nf++) {
                    mma_f16(acc[mf][nf], ah, bh[nf]);
                    mma_f16(acc[mf][nf], al, bh[nf]);
                }
            }
        }
        __syncthreads();
    }

    const int r_lo = nt * 128 + wm * 32 + (lane >> 2);
    const int c_base = wn * 32 + (lane & 3) * 2;
    float* Pz = g_p + (size_t)z * NN * 64;
#pragma unroll
    for (int mf = 0; mf < 2; mf++) {
        int rg0 = r_lo + mf * 16;
#pragma unroll
        for (int nf = 0; nf < 4; nf++) {
            int cg = c_base + nf * 8;
            *(float2*)(Pz + (size_t)rg0 * 64 + cg)       = make_float2(acc[mf][nf][0], acc[mf][nf][1]);
            *(float2*)(Pz + (size_t)(rg0 + 8) * 64 + cg) = make_float2(acc[mf][nf][2], acc[mf][nf][3]);
        }
    }
}

// ===========================================================================
// psum: 2-phase parallel reduction
// ===========================================================================
__global__ __launch_bounds__(256) void psum_part_kernel()
{
    __shared__ float red[4][64];
    const int z = blockIdx.x, seg = blockIdx.y;
    const int d = threadIdx.x & 63, sub = threadIdx.x >> 6;
    const float* p = g_p + ((size_t)z * NN + seg * 256 + sub * 64) * 64 + d;
    float s = 0.f;
#pragma unroll 8
    for (int n = 0; n < 64; n++) s += p[(size_t)n * 64];
    red[sub][d] = s;
    __syncthreads();
    if (threadIdx.x < 64)
        g_psumP[z][seg][d] = red[0][d] + red[1][d] + red[2][d] + red[3][d];
}
__global__ __launch_bounds__(256) void psum_red_kernel()
{
    const int i = blockIdx.x * 256 + threadIdx.x;
    const int z = i >> 6, d = i & 63;
    float s = 0.f;
#pragma unroll
    for (int g = 0; g < 8; g++) s += g_psumP[z][g][d];
    g_psum[z * 64 + d] = s;
}

// ===========================================================================
// dots = scale*(Qh+Ql)@Kh^T (+col mask) on COMPACTED rows -> pre
// (round-13 proven layout: MMA guarded by row0<cnt, register-direct epilogue)
// ===========================================================================
#define DSTAGE 24576u
#define DOTS_SMEM (4 * 24576)

__global__ __launch_bounds__(256, 2) void dots_gemm(float* __restrict__ Out)
{
    extern __shared__ char sm[];
    __shared__ int cmask[128];
    const uint32_t sbase = smem_u32(sm);

    const int tid = threadIdx.x;
    const int wid = tid >> 5, lane = tid & 31;
    const int wm = wid >> 2, wn = wid & 3;
    const int z = blockIdx.z, b = z >> 3;
    const int row0 = blockIdx.y * 128, col0 = blockIdx.x * 128;

    const int cnt = g_validcnt[b];

    float acc[4][4][4];

    if (row0 < cnt) {
        if (tid < 128) cmask[tid] = g_mask[b * NN + col0 + tid];

        const char* qhB = (const char*)g_qh + (((size_t)z * 16 + blockIdx.y) * 16) * 8192;
        const char* qlB = (const char*)g_ql + (((size_t)z * 16 + blockIdx.y) * 16) * 8192;
        const char* khB = (const char*)g_kh + (((size_t)z * 16 + blockIdx.x) * 16) * 8192;

#pragma unroll
        for (int mf = 0; mf < 4; mf++)
#pragma unroll
            for (int nf = 0; nf < 4; nf++)
#pragma unroll
                for (int r = 0; r < 4; r++) acc[mf][nf][r] = 0.f;

        auto issue = [&](int ch) {
            const uint32_t ss = sbase + (uint32_t)(ch & 3) * DSTAGE;
            const char* q1 = qhB + (size_t)ch * 8192;
            const char* l1 = qlB + (size_t)ch * 8192;
            const char* k1 = khB + (size_t)ch * 8192;
#pragma unroll
            for (int k = 0; k < 2; k++) {
                uint32_t off = (uint32_t)(tid + k * 256) * 16;
                CP16(ss + off,         q1 + off);
                CP16(ss + 8192 + off,  l1 + off);
                CP16(ss + 16384 + off, k1 + off);
            }
        };

        issue(0); CP_COMMIT();
        issue(1); CP_COMMIT();
        issue(2); CP_COMMIT();

        const uint32_t a_row = (uint32_t)(wm * 64) + (lane & 15);
        const uint32_t a_kb  = ((lane >> 4) & 1) * 16;
        const uint32_t b_row = (uint32_t)(wn * 32) + ((lane >> 4) & 1) * 8 + (lane & 7);
        const uint32_t b_kb  = ((lane >> 3) & 1) * 16;

        for (int ch = 0; ch < 16; ++ch) {
            CP_WAIT2();
            __syncthreads();
            const uint32_t S = sbase + (uint32_t)(ch & 3) * DSTAGE;
            const uint32_t AH = S, AL = S + 8192, BH = S + 16384;
#pragma unroll
            for (int ks = 0; ks < 2; ks++) {
                const uint32_t kb0 = (uint32_t)ks * 32;
                uint32_t bh[4][2];
#pragma unroll
                for (int p = 0; p < 2; p++) {
                    uint32_t o = swz(b_row + p * 16, kb0 + b_kb);
                    uint32_t t4[4];
                    ldsm_x4(t4, BH + o);
                    bh[2*p][0] = t4[0]; bh[2*p][1] = t4[1];
                    bh[2*p+1][0] = t4[2]; bh[2*p+1][1] = t4[3];
                }
#pragma unroll
                for (int mf = 0; mf < 4; mf++) {
                    uint32_t o = swz(a_row + mf * 16, kb0 + a_kb);
                    uint32_t ah[4], al[4];
                    ldsm_x4(ah, AH + o);
                    ldsm_x4(al, AL + o);
#pragma unroll
                    for (int nf = 0; nf < 4; nf++) {
                        mma_f16(acc[mf][nf], ah, bh[nf]);
                        mma_f16(acc[mf][nf], al, bh[nf]);
                    }
                }
            }
            if (ch + 3 < 16) issue(ch + 3);
            CP_COMMIT();
        }
    }

    // epilogue: valid rows -> scaled/masked result; rows >= cnt -> MASKV fill
    const int r_lo = row0 + wm * 64 + (lane >> 2);
    const int c_base = wn * 32 + (lane & 3) * 2;
    float* outz = Out + (size_t)z * NN * NN;
#pragma unroll
    for (int mf = 0; mf < 4; mf++) {
#pragma unroll
        for (int rr = 0; rr < 2; rr++) {
            const int cr = r_lo + mf * 16 + rr * 8;
            if (cr < cnt) {
                const int orig = g_rowmap[b][cr];
                float* rowp = outz + (size_t)orig * NN + col0;
#pragma unroll
                for (int nf = 0; nf < 4; nf++) {
                    int cg = c_base + nf * 8;
                    float2 v;
                    v.x = cmask[cg]     ? acc[mf][nf][rr*2+0] * SCALE : MASKV;
                    v.y = cmask[cg + 1] ? acc[mf][nf][rr*2+1] * SCALE : MASKV;
                    __stcs((float2*)(rowp + cg), v);
                }
            } else {
                const int orig = g_maskedmap[b][cr - cnt];
                float* rowp = outz + (size_t)orig * NN + col0;
                const float2 mv = make_float2(MASKV, MASKV);
#pragma unroll
                for (int nf = 0; nf < 4; nf++)
                    __stcs((float2*)(rowp + c_base + nf * 8), mv);
            }
        }
    }
}

// ===========================================================================
// entmax-1.5: streaming loads/stores; Newton with uniform early-exit
// ===========================================================================
__global__ __launch_bounds__(256) void entmax_kernel(
    const float* __restrict__ pre, float* __restrict__ att)
{
    const int wid = threadIdx.x >> 5, lane = threadIdx.x & 31;
    const size_t row = (size_t)blockIdx.x * 8 + wid;
    const int z = (int)(row >> 11), n = (int)(row & 2047), b = z >> 3;
    float4* o4 = (float4*)(att + row * NN);

    if (!g_mask[b * NN + n]) {
        const float P = 1.0f / 2048.0f;
        float4 u = make_float4(P, P, P, P);
#pragma unroll
        for (int i = 0; i < 16; i++) __stcs(&o4[lane + i * 32], u);
        if (lane == 0) g_cnt[row] = -1;
        return;
    }

    const float4* p4 = (const float4*)(pre + row * NN);
    float x[64];
    float mx = -3.0e38f;
#pragma unroll
    for (int i = 0; i < 16; i++) {
        float4 v = __ldcs(&p4[lane + i * 32]);
        x[4*i+0] = 0.5f * v.x; x[4*i+1] = 0.5f * v.y;
        x[4*i+2] = 0.5f * v.z; x[4*i+3] = 0.5f * v.w;
        mx = fmaxf(mx, fmaxf(fmaxf(x[4*i], x[4*i+1]), fmaxf(x[4*i+2], x[4*i+3])));
    }
#pragma unroll
    for (int off = 16; off; off >>= 1)
        mx = fmaxf(mx, __shfl_xor_sync(0xffffffffu, mx, off));
#pragma unroll
    for (int j = 0; j < 64; j++) x[j] -= mx;

    float tau = -1.0f;
#pragma unroll 1
    for (int it = 0; it < 12; ++it) {
        float s1 = 0.f, s2 = 0.f;
#pragma unroll
        for (int j = 0; j < 64; j++) {
            float d = fmaxf(x[j] - tau, 0.f);
            s1 += d;
            s2 = fmaf(d, d, s2);
        }
#pragma unroll
        for (int off = 16; off; off >>= 1) {
            s1 += __shfl_xor_sync(0xffffffffu, s1, off);
            s2 += __shfl_xor_sync(0xffffffffu, s2, off);
        }
        float step = (s1 > 1e-20f) ? (s2 - 1.0f) / (2.0f * s1) : 0.f;
        tau += step;
        if (fabsf(step) < 1e-6f) break;
    }

#pragma unroll
    for (int i = 0; i < 16; i++) {
        float4 w;
        float d;
        d = fmaxf(x[4*i+0] - tau, 0.f); w.x = d * d;
        d = fmaxf(x[4*i+1] - tau, 0.f); w.y = d * d;
        d = fmaxf(x[4*i+2] - tau, 0.f); w.z = d * d;
        d = fmaxf(x[4*i+3] - tau, 0.f); w.w = d * d;
        __stcs(&o4[lane + i * 32], w);
    }

    int cl = 0;
#pragma unroll
    for (int j = 0; j < 64; j++) cl += (x[j] > tau) ? 1 : 0;
    int v = cl;
#pragma unroll
    for (int d = 1; d < 32; d <<= 1) {
        int t = __shfl_up_sync(0xffffffffu, v, d);
        if (lane >= d) v += t;
    }
    int total = __shfl_sync(0xffffffffu, v, 31);
    int pos = v - cl;
    if (total <= MAXS) {
        int*   si = g_si + row * MAXS;
        float* sw = g_sw + row * MAXS;
#pragma unroll
        for (int i = 0; i < 16; i++)
#pragma unroll
            for (int c = 0; c < 4; c++) {
                int j = 4*i + c;
                if (x[j] > tau) {
                    float d = x[j] - tau;
                    si[pos] = 4*lane + 128*i + c;
                    sw[pos] = d * d;
                    pos++;
                }
            }
        if (lane == 31) g_cnt[row] = total;
    } else if (lane == 31) {
        g_cnt[row] = -2;
    }
}

// ===========================================================================
// Fused sparse attention-out: 4-wide unrolled gather (prefetched idx/weights)
// ===========================================================================
__global__ __launch_bounds__(256) void af_kernel(
    const float* __restrict__ att, const float* __restrict__ bo, float* __restrict__ out)
{
    const int wid = threadIdx.x >> 5, lane = threadIdx.x & 31;
    const int gw = blockIdx.x * 8 + wid;
    const int b = gw >> 11, n = gw & 2047;
    const int dc = lane * 2;

    float2 acc;
    float2 bb = *(const float2*)(bo + dc);
    acc.x = bb.x; acc.y = bb.y;

#pragma unroll 1
    for (int h = 0; h < HH; h++) {
        const int z = b * HH + h;
        const size_t row = (size_t)z * NN + n;
        const int cnt = g_cnt[row];
        const float* Pz = g_p + (size_t)z * NN * 64;
        if (cnt == -1) {
            const float Pu = 1.0f / 2048.0f;
            float2 s = *(const float2*)(g_psum + z * 64 + dc);
            acc.x = fmaf(Pu, s.x, acc.x);
            acc.y = fmaf(Pu, s.y, acc.y);
        } else if (cnt >= 0) {
            const int*   si = g_si + row * MAXS;
            const float* sw = g_sw + row * MAXS;
            int j = 0;
            for (; j + 4 <= cnt; j += 4) {
                int   i0 = si[j],   i1 = si[j+1], i2 = si[j+2], i3 = si[j+3];
                float w0 = sw[j],   w1 = sw[j+1], w2 = sw[j+2], w3 = sw[j+3];
                float2 v0 = *(const float2*)(Pz + (size_t)i0 * 64 + dc);
                float2 v1 = *(const float2*)(Pz + (size_t)i1 * 64 + dc);
                float2 v2 = *(const float2*)(Pz + (size_t)i2 * 64 + dc);
                float2 v3 = *(const float2*)(Pz + (size_t)i3 * 64 + dc);
                acc.x = fmaf(w0, v0.x, acc.x); acc.y = fmaf(w0, v0.y, acc.y);
                acc.x = fmaf(w1, v1.x, acc.x); acc.y = fmaf(w1, v1.y, acc.y);
                acc.x = fmaf(w2, v2.x, acc.x); acc.y = fmaf(w2, v2.y, acc.y);
                acc.x = fmaf(w3, v3.x, acc.x); acc.y = fmaf(w3, v3.y, acc.y);
            }
            for (; j < cnt; j++) {
                int   i0 = si[j];
                float w0 = sw[j];
                float2 v0 = *(const float2*)(Pz + (size_t)i0 * 64 + dc);
                acc.x = fmaf(w0, v0.x, acc.x);
                acc.y = fmaf(w0, v0.y, acc.y);
            }
        } else {
            const float* arow = att + row * NN;
            for (int c = 0; c < NN; c++) {
                float p = __ldcs(arow + c);
                if (p != 0.f) {
                    float2 v = *(const float2*)(Pz + (size_t)c * 64 + dc);
                    acc.x = fmaf(p, v.x, acc.x);
                    acc.y = fmaf(p, v.y, acc.y);
                }
            }
        }
    }
    *(float2*)(out + (size_t)gw * 64 + dc) = acc;
}

// ===========================================================================
extern "C" void kernel_launch(void* const* d_in, const int* in_sizes, int n_in,
                              void* d_out, int out_size)
{
    const float* x   = (const float*)d_in[0];
    const unsigned char* mask_raw = (const unsigned char*)d_in[1];
    const float* Wq  = (const float*)d_in[2];
    const float* Wk  = (const float*)d_in[3];
    const float* Wv  = (const float*)d_in[4];
    const float* Wo  = (const float*)d_in[5];
    const float* bo  = (const float*)d_in[6];

    float* out = (float*)d_out;
    float* pre = out + OUT_ELEMS;
    float* att = pre + PRE_ELEMS;

    static int smem_set = 0;
    if (!smem_set) {
        cudaFuncSetAttribute(dots_gemm,
                             cudaFuncAttributeMaxDynamicSharedMemorySize, DOTS_SMEM);
        cudaFuncSetAttribute(proj_mma,
                             cudaFuncAttributeMaxDynamicSharedMemorySize, PROJ_SMEM);
        cudaFuncSetAttribute(pvw_mma,
                             cudaFuncAttributeMaxDynamicSharedMemorySize, PVW_SMEM);
        smem_set = 1;
    }

    prep_compact_kernel<<<1, 256>>>(mask_raw);

    conv_all_kernel<<<1088, 256>>>(x, Wq, Wk, Wv, Wo);

    proj_mma<<<dim3(96, 32), 256, PROJ_SMEM>>>();

    pvw_mma<<<dim3(16, 16), 256, PVW_SMEM>>>();
    psum_part_kernel<<<dim3(16, 8), 256>>>();
    psum_red_kernel<<<4, 256>>>();

    dots_gemm<<<dim3(16, 16, 16), 256, DOTS_SMEM>>>(pre);

    entmax_kernel<<<BB * HH * NN / 8, 256>>>(pre, att);

    af_kernel<<<BB * NN / 8, 256>>>(att, bo, out);
}

// round 17
// speedup vs baseline: 1.1516x; 1.0221x over previous
#include <cuda_runtime.h>
#include <cuda_bf16.h>
#include <cuda_fp16.h>
#include <cstdint>

// Problem constants
#define BB 2
#define NN 2048
#define DIMX 64
#define HH 8
#define DD 512            // per-head dim
#define INNER 4096
#define SCALE 0.125f
#define MASKV -1e9f

#define OUT_ELEMS   (BB*NN*DIMX)          // 262144
#define PRE_ELEMS   (BB*HH*NN*NN)         // 67108864

#define NROWS (BB*HH*NN)   // 32768
#define NZ    (BB*HH)      // 16
#define MAXS  512

// Scratch
__device__ __half g_qh[BB*HH*NN*DD];
__device__ __half g_ql[BB*HH*NN*DD];
__device__ __half g_kh[BB*HH*NN*DD];
__device__ __half g_vh[BB*HH*NN*DD];
__device__ __half g_vl[BB*HH*NN*DD];
__device__ __half g_xh[4096*64];
__device__ __half g_xl[4096*64];
__device__ __half g_wh[12288*64];
__device__ __half g_wl[12288*64];
__device__ __half g_wo[HH*64*DD];
__device__ float  g_p[(size_t)NZ * NN * 64];
__device__ float  g_psum[NZ * 64];
__device__ float  g_psumP[NZ][8][64];
__device__ int    g_mask[BB*NN];
__device__ int    g_slot[BB*NN];         // n -> compact slot (-1 if masked)
__device__ int    g_rowmap[BB][NN];      // compact slot -> n (valid rows)
__device__ int    g_maskedmap[BB][NN];   // masked slot -> n (masked rows)
__device__ int    g_validcnt[BB];
__device__ int    g_si[(size_t)NROWS * MAXS];
__device__ float  g_sw[(size_t)NROWS * MAXS];
__device__ int    g_cnt[NROWS];

// ===========================================================================
// Helpers
// ===========================================================================
__device__ __forceinline__ uint32_t smem_u32(const void* p) {
    uint32_t r;
    asm("{ .reg .u64 t; cvta.to.shared.u64 t, %1; cvt.u32.u64 %0, t; }" : "=r"(r) : "l"(p));
    return r;
}
__device__ __forceinline__ void ldsm_x4(uint32_t* r, uint32_t addr) {
    asm volatile("ldmatrix.sync.aligned.m8n8.x4.shared.b16 {%0,%1,%2,%3}, [%4];"
        : "=r"(r[0]), "=r"(r[1]), "=r"(r[2]), "=r"(r[3]) : "r"(addr));
}
__device__ __forceinline__ void mma_f16(float* c, const uint32_t* a, const uint32_t* b) {
    asm volatile("mma.sync.aligned.m16n8k16.row.col.f32.f16.f16.f32 "
        "{%0,%1,%2,%3}, {%4,%5,%6,%7}, {%8,%9}, {%0,%1,%2,%3};"
        : "+f"(c[0]), "+f"(c[1]), "+f"(c[2]), "+f"(c[3])
        : "r"(a[0]), "r"(a[1]), "r"(a[2]), "r"(a[3]), "r"(b[0]), "r"(b[1]));
}
#define CP16(saddr, gptr) \
    asm volatile("cp.async.cg.shared.global [%0], [%1], 16;" :: "r"(saddr), "l"(gptr))
#define CP_COMMIT() asm volatile("cp.async.commit_group;")
#define CP_WAIT2()  asm volatile("cp.async.wait_group 2;")
#define CP_WAIT1()  asm volatile("cp.async.wait_group 1;")
#define CP_WAIT0()  asm volatile("cp.async.wait_group 0;")

__device__ __forceinline__ uint32_t swz(uint32_t r, uint32_t kb) {
    uint32_t off = r * 64u + kb;
    return off ^ ((off >> 3) & 0x70u);
}
__device__ __forceinline__ void split4h(float4 v, uint2& hh, uint2& ll) {
    __half2 h01 = __floats2half2_rn(v.x, v.y);
    __half2 h23 = __floats2half2_rn(v.z, v.w);
    float2 f01 = __half22float2(h01);
    float2 f23 = __half22float2(h23);
    __half2 l01 = __floats2half2_rn(v.x - f01.x, v.y - f01.y);
    __half2 l23 = __floats2half2_rn(v.z - f23.x, v.w - f23.y);
    hh.x = *(uint32_t*)&h01; hh.y = *(uint32_t*)&h23;
    ll.x = *(uint32_t*)&l01; ll.y = *(uint32_t*)&l23;
}

// ===========================================================================
// prep_mask + compact merged (single block)
// ===========================================================================
__global__ __launch_bounds__(256) void prep_compact_kernel(const unsigned char* __restrict__ raw) {
    __shared__ int cnt_f32, cnt_gt1;
    __shared__ int ps[256];
    if (threadIdx.x == 0) { cnt_f32 = 0; cnt_gt1 = 0; }
    __syncthreads();
    const unsigned int* u = (const unsigned int*)raw;
    int lf = 0, lg = 0;
    for (int i = threadIdx.x; i < 1024; i += blockDim.x) {
        unsigned int v = u[i];
        if (v == 0x3f800000u) lf++;
        else if (v > 1u) lg++;
    }
    atomicAdd(&cnt_f32, lf);
    atomicAdd(&cnt_gt1, lg);
    __syncthreads();
    int mode;
    if (cnt_f32 > 64) mode = 2;
    else if (cnt_gt1 > 64) mode = 1;
    else mode = 0;
    for (int i = threadIdx.x; i < BB*NN; i += blockDim.x) {
        int m;
        if (mode == 2)      m = (((const unsigned int*)raw)[i] != 0u) ? 1 : 0;
        else if (mode == 1) m = raw[i] ? 1 : 0;
        else                m = (((const int*)raw)[i] != 0) ? 1 : 0;
        g_mask[i] = m;
    }
    __syncthreads();

    for (int b = 0; b < BB; b++) {
        const int base_n = threadIdx.x * 8;
        int m[8], s = 0;
#pragma unroll
        for (int i = 0; i < 8; i++) { m[i] = g_mask[b * NN + base_n + i]; s += m[i]; }
        ps[threadIdx.x] = s;
        __syncthreads();
        for (int off = 1; off < 256; off <<= 1) {
            int v = ps[threadIdx.x];
            int u2 = (threadIdx.x >= off) ? ps[threadIdx.x - off] : 0;
            __syncthreads();
            ps[threadIdx.x] = v + u2;
            __syncthreads();
        }
        int pos = threadIdx.x ? ps[threadIdx.x - 1] : 0;
#pragma unroll
        for (int i = 0; i < 8; i++) {
            int n = base_n + i;
            if (m[i]) {
                g_rowmap[b][pos] = n;
                g_slot[b * NN + n] = pos;
                pos++;
            } else {
                g_maskedmap[b][n - pos] = n;
                g_slot[b * NN + n] = -1;
            }
        }
        if (threadIdx.x == 255) g_validcnt[b] = ps[255];
        __syncthreads();
    }
}

// ===========================================================================
// conv_all: fused conv_x (blocks 0..255), conv_w (256..1023), conv_wo (1024..1087)
// ===========================================================================
__global__ __launch_bounds__(256) void conv_all_kernel(
    const float* __restrict__ X,
    const float* __restrict__ Wq, const float* __restrict__ Wk, const float* __restrict__ Wv,
    const float* __restrict__ Wo)
{
    __shared__ float sh[64 * 65];
    const int bx = blockIdx.x;
    if (bx < 256) {
        int idx = bx * 256 + threadIdx.x;
        int m = idx >> 4;
        int k = (idx & 15) * 4;
        float4 v = ((const float4*)X)[idx];
        uint2 hh, ll;
        split4h(v, hh, ll);
        size_t tb = ((size_t)(m >> 7) * 2 + (k >> 5)) * 8192;
        uint32_t so = swz((uint32_t)(m & 127), (uint32_t)(k & 31) * 2);
        *(uint2*)((char*)g_xh + tb + so) = hh;
        *(uint2*)((char*)g_xl + tb + so) = ll;
    } else if (bx < 1024) {
        float (*t)[33] = (float(*)[33])sh;
        const int i = bx - 256;
        const int kt = i / 384;
        const int n0 = (i % 384) * 32;
        const float* W = (n0 < 4096) ? Wq : (n0 < 8192) ? Wk : Wv;
        const int nl0 = n0 & 4095;
        const int tx = threadIdx.x & 31, ty8 = threadIdx.x >> 5;
#pragma unroll
        for (int j = 0; j < 4; j++) {
            int kk = ty8 + j * 8;
            t[kk][tx] = W[(size_t)(kt * 32 + kk) * 4096 + nl0 + tx];
        }
        __syncthreads();
        const int nn = threadIdx.x >> 3;
        const int k4 = (threadIdx.x & 7) * 4;
        float4 v = make_float4(t[k4][nn], t[k4+1][nn], t[k4+2][nn], t[k4+3][nn]);
        uint2 hh, ll;
        split4h(v, hh, ll);
        const int gn = n0 + nn;
        const int gk = kt * 32 + k4;
        size_t tb = ((size_t)(gn >> 7) * 2 + (gk >> 5)) * 8192;
        uint32_t so = swz((uint32_t)(gn & 127), (uint32_t)(gk & 31) * 2);
        *(uint2*)((char*)g_wh + tb + so) = hh;
        *(uint2*)((char*)g_wl + tb + so) = ll;
    } else {
        float (*t)[65] = (float(*)[65])sh;
        const int i = bx - 1024;
        const int h = i >> 3;
        const int d0 = (i & 7) * 64;
#pragma unroll
        for (int j = 0; j < 16; j++) {
            int idx = threadIdx.x + j * 256;
            int dl = idx >> 6, dc = idx & 63;
            t[dl][dc] = Wo[(size_t)(h * 512 + d0 + dl) * 64 + dc];
        }
        __syncthreads();
#pragma unroll
        for (int j = 0; j < 4; j++) {
            int jj = threadIdx.x + j * 256;
            int dc = jj >> 4;
            int d4 = (jj & 15) * 4;
            __half2 h01 = __floats2half2_rn(t[d4+0][dc], t[d4+1][dc]);
            __half2 h23 = __floats2half2_rn(t[d4+2][dc], t[d4+3][dc]);
            uint2 hv;
            hv.x = *(uint32_t*)&h01; hv.y = *(uint32_t*)&h23;
            const int d = d0 + d4;
            size_t tb = ((size_t)h * 16 + (d >> 5)) * 4096;
            uint32_t so = swz((uint32_t)dc, (uint32_t)(d & 31) * 2);
            *(uint2*)((char*)g_wo + tb + so) = hv;
        }
    }
}

// ===========================================================================
// proj_mma: C = x @ [Wq|Wk|Wv], 3-term fp16 split, 2-chunk pipelined.
// Epilogue: SMEM repack -> uint4 stores. Q rows at compact slot.
// ===========================================================================
#define PROJ_SMEM 67584

__global__ __launch_bounds__(256, 2) void proj_mma()
{
    extern __shared__ char sm[];
    const uint32_t sbase = smem_u32(sm);
    const int tid = threadIdx.x;
    const int wid = tid >> 5, lane = tid & 31;
    const int wm = wid >> 2, wn = wid & 3;
    const int row0 = blockIdx.y * 128;
    const int col0 = blockIdx.x * 128;

    const char* xhB = (const char*)g_xh + (size_t)(blockIdx.y * 2) * 8192;
    const char* xlB = (const char*)g_xl + (size_t)(blockIdx.y * 2) * 8192;
    const char* whB = (const char*)g_wh + (size_t)(blockIdx.x * 2) * 8192;
    const char* wlB = (const char*)g_wl + (size_t)(blockIdx.x * 2) * 8192;

    auto issue = [&](int chk) {
        const uint32_t co = (uint32_t)chk * 8192;
#pragma unroll
        for (int k = 0; k < 2; k++) {
            uint32_t off = (uint32_t)(tid + k * 256) * 16;
            CP16(sbase + co + off,          xhB + co + off);
            CP16(sbase + 16384 + co + off,  xlB + co + off);
            CP16(sbase + 32768 + co + off,  whB + co + off);
            CP16(sbase + 49152 + co + off,  wlB + co + off);
        }
    };
    issue(0); CP_COMMIT();
    issue(1); CP_COMMIT();

    float acc[4][4][4];
#pragma unroll
    for (int mf = 0; mf < 4; mf++)
#pragma unroll
        for (int nf = 0; nf < 4; nf++)
#pragma unroll
            for (int r = 0; r < 4; r++) acc[mf][nf][r] = 0.f;

    const uint32_t a_row = (uint32_t)(wm * 64) + (lane & 15);
    const uint32_t a_kb  = ((lane >> 4) & 1) * 16;
    const uint32_t b_row = (uint32_t)(wn * 32) + ((lane >> 4) & 1) * 8 + (lane & 7);
    const uint32_t b_kb  = ((lane >> 3) & 1) * 16;

#pragma unroll
    for (int chk = 0; chk < 2; chk++) {
        if (chk == 0) CP_WAIT1(); else CP_WAIT0();
        __syncthreads();
        const uint32_t AH = sbase + (uint32_t)chk * 8192;
        const uint32_t AL = AH + 16384;
        const uint32_t BH = sbase + 32768 + (uint32_t)chk * 8192;
        const uint32_t BL = BH + 16384;
#pragma unroll
        for (int ks = 0; ks < 2; ks++) {
            const uint32_t kb0 = (uint32_t)ks * 32;
            uint32_t bh[4][2], bl[4][2];
#pragma unroll
            for (int p = 0; p < 2; p++) {
                uint32_t o = swz(b_row + p * 16, kb0 + b_kb);
                uint32_t t4[4];
                ldsm_x4(t4, BH + o);
                bh[2*p][0] = t4[0]; bh[2*p][1] = t4[1];
                bh[2*p+1][0] = t4[2]; bh[2*p+1][1] = t4[3];
                ldsm_x4(t4, BL + o);
                bl[2*p][0] = t4[0]; bl[2*p][1] = t4[1];
                bl[2*p+1][0] = t4[2]; bl[2*p+1][1] = t4[3];
            }
#pragma unroll
            for (int mf = 0; mf < 4; mf++) {
                uint32_t o = swz(a_row + mf * 16, kb0 + a_kb);
                uint32_t ah[4], al[4];
                ldsm_x4(ah, AH + o);
                ldsm_x4(al, AL + o);
#pragma unroll
                for (int nf = 0; nf < 4; nf++) {
                    mma_f16(acc[mf][nf], ah, bh[nf]);
                    mma_f16(acc[mf][nf], ah, bl[nf]);
                    mma_f16(acc[mf][nf], al, bh[nf]);
                }
            }
        }
    }

    // repack through SMEM
    __syncthreads();
    float* sacc = (float*)sm;   // [128][132]
    {
        const int rb = wm * 64 + (lane >> 2);
        const int cb = wn * 32 + (lane & 3) * 2;
#pragma unroll
        for (int mf = 0; mf < 4; mf++)
#pragma unroll
            for (int nf = 0; nf < 4; nf++)
#pragma unroll
                for (int rr = 0; rr < 2; rr++) {
                    int r = rb + mf * 16 + rr * 8;
                    int c = cb + nf * 8;
                    *(float2*)(sacc + r * 132 + c) =
                        make_float2(acc[mf][nf][rr*2+0], acc[mf][nf][rr*2+1]);
                }
    }
    __syncthreads();

    const int wsel = col0 >> 12;           // 0=Q 1=K 2=V
    const int dcol0 = col0 & 4095;
    const int r = tid >> 1;
    const int cH = (tid & 1) * 64;
    const int m = row0 + r;
    const int b = m >> 11, n = m & 2047;
    int nrow = n;
    if (wsel == 0) nrow = g_slot[b * NN + n];
    if (wsel != 0 || nrow >= 0) {
        const float* rowp = sacc + r * 132 + cH;
#pragma unroll
        for (int g = 0; g < 8; g++) {
            const int cg = cH + g * 8;
            const int col = dcol0 + cg;
            const int h = col >> 9, dd = col & 511;
            float4 e0 = *(const float4*)(rowp + g * 8);
            float4 e1 = *(const float4*)(rowp + g * 8 + 4);
            __half2 h0 = __floats2half2_rn(e0.x, e0.y);
            __half2 h1 = __floats2half2_rn(e0.z, e0.w);
            __half2 h2 = __floats2half2_rn(e1.x, e1.y);
            __half2 h3 = __floats2half2_rn(e1.z, e1.w);
            uint4 hv = make_uint4(*(uint32_t*)&h0, *(uint32_t*)&h1,
                                  *(uint32_t*)&h2, *(uint32_t*)&h3);
            size_t tb = (((size_t)(b*HH+h) * 16 + (nrow >> 7)) * 16 + (dd >> 5)) * 8192;
            uint32_t so = swz((uint32_t)(nrow & 127), (uint32_t)(dd & 31) * 2);
            if (wsel == 1) {
                *(uint4*)((char*)g_kh + tb + so) = hv;
            } else {
                float2 f0 = __half22float2(h0), f1 = __half22float2(h1);
                float2 f2 = __half22float2(h2), f3 = __half22float2(h3);
                __half2 l0 = __floats2half2_rn(e0.x - f0.x, e0.y - f0.y);
                __half2 l1 = __floats2half2_rn(e0.z - f1.x, e0.w - f1.y);
                __half2 l2 = __floats2half2_rn(e1.x - f2.x, e1.y - f2.y);
                __half2 l3 = __floats2half2_rn(e1.z - f3.x, e1.w - f3.y);
                uint4 lv = make_uint4(*(uint32_t*)&l0, *(uint32_t*)&l1,
                                      *(uint32_t*)&l2, *(uint32_t*)&l3);
                if (wsel == 0) {
                    *(uint4*)((char*)g_qh + tb + so) = hv;
                    *(uint4*)((char*)g_ql + tb + so) = lv;
                } else {
                    *(uint4*)((char*)g_vh + tb + so) = hv;
                    *(uint4*)((char*)g_vl + tb + so) = lv;
                }
            }
        }
    }
}

// ===========================================================================
// pvw_mma: P[z] = (Vh+Vl) @ Woh^T
// ===========================================================================
#define PVW_STAGE 20480u
#define PVW_SMEM (2 * 20480)

__global__ __launch_bounds__(256, 2) void pvw_mma()
{
    extern __shared__ char sm[];
    const uint32_t sbase = smem_u32(sm);
    const int tid = threadIdx.x;
    const int wid = tid >> 5, lane = tid & 31;
    const int wm = wid >> 1, wn = wid & 1;
    const int z = blockIdx.y, h = z & 7;
    const int nt = blockIdx.x;

    const char* vhB = (const char*)g_vh + (((size_t)z * 16 + nt) * 16) * 8192;
    const char* vlB = (const char*)g_vl + (((size_t)z * 16 + nt) * 16) * 8192;
    const char* woB = (const char*)g_wo + (size_t)(h * 16) * 4096;

    float acc[2][4][4];
#pragma unroll
    for (int mf = 0; mf < 2; mf++)
#pragma unroll
        for (int nf = 0; nf < 4; nf++)
#pragma unroll
            for (int r = 0; r < 4; r++) acc[mf][nf][r] = 0.f;

    auto issue = [&](int ch) {
        const uint32_t ss = sbase + (uint32_t)(ch & 1) * PVW_STAGE;
#pragma unroll
        for (int k = 0; k < 2; k++) {
            uint32_t off = (uint32_t)(tid + k * 256) * 16;
            CP16(ss + off,        vhB + (size_t)ch * 8192 + off);
            CP16(ss + 8192 + off, vlB + (size_t)ch * 8192 + off);
        }
        {
            uint32_t off = (uint32_t)tid * 16;
            CP16(ss + 16384 + off, woB + (size_t)ch * 4096 + off);
        }
    };

    issue(0); CP_COMMIT();

    const uint32_t a_row = (uint32_t)(wm * 32) + (lane & 15);
    const uint32_t a_kb  = ((lane >> 4) & 1) * 16;
    const uint32_t b_row = (uint32_t)(wn * 32) + ((lane >> 4) & 1) * 8 + (lane & 7);
    const uint32_t b_kb  = ((lane >> 3) & 1) * 16;

    for (int ch = 0; ch < 16; ++ch) {
        if (ch + 1 < 16) { issue(ch + 1); CP_COMMIT(); CP_WAIT1(); }
        else CP_WAIT0();
        __syncthreads();
        const uint32_t S = sbase + (uint32_t)(ch & 1) * PVW_STAGE;
        const uint32_t AH = S, AL = S + 8192, BH = S + 16384;
#pragma unroll
        for (int ks = 0; ks < 2; ks++) {
            const uint32_t kb0 = (uint32_t)ks * 32;
            uint32_t bh[4][2];
#pragma unroll
            for (int p = 0; p < 2; p++) {
                uint32_t o = swz(b_row + p * 16, kb0 + b_kb);
                uint32_t t4[4];
                ldsm_x4(t4, BH + o);
                bh[2*p][0] = t4[0]; bh[2*p][1] = t4[1];
                bh[2*p+1][0] = t4[2]; bh[2*p+1][1] = t4[3];
            }
#pragma unroll
            for (int mf = 0; mf < 2; mf++) {
                uint32_t o = swz(a_row + mf * 16, kb0 + a_kb);
                uint32_t ah[4], al[4];
                ldsm_x4(ah, AH + o);
                ldsm_x4(al, AL + o);
#pragma unroll
                for (int nf = 0; nf < 4; nf++) {
                    mma_f16(acc[mf][nf], ah, bh[nf]);
                    mma_f16(acc[mf][nf], al, bh[nf]);
                }
            }
        }
        __syncthreads();
    }

    const int r_lo = nt * 128 + wm * 32 + (lane >> 2);
    const int c_base = wn * 32 + (lane & 3) * 2;
    float* Pz = g_p + (size_t)z * NN * 64;
#pragma unroll
    for (int mf = 0; mf < 2; mf++) {
        int rg0 = r_lo + mf * 16;
#pragma unroll
        for (int nf = 0; nf < 4; nf++) {
            int cg = c_base + nf * 8;
            *(float2*)(Pz + (size_t)rg0 * 64 + cg)       = make_float2(acc[mf][nf][0], acc[mf][nf][1]);
            *(float2*)(Pz + (size_t)(rg0 + 8) * 64 + cg) = make_float2(acc[mf][nf][2], acc[mf][nf][3]);
        }
    }
}

// ===========================================================================
// psum: 2-phase parallel reduction
// ===========================================================================
__global__ __launch_bounds__(256) void psum_part_kernel()
{
    __shared__ float red[4][64];
    const int z = blockIdx.x, seg = blockIdx.y;
    const int d = threadIdx.x & 63, sub = threadIdx.x >> 6;
    const float* p = g_p + ((size_t)z * NN + seg * 256 + sub * 64) * 64 + d;
    float s = 0.f;
#pragma unroll 8
    for (int n = 0; n < 64; n++) s += p[(size_t)n * 64];
    red[sub][d] = s;
    __syncthreads();
    if (threadIdx.x < 64)
        g_psumP[z][seg][d] = red[0][d] + red[1][d] + red[2][d] + red[3][d];
}
__global__ __launch_bounds__(256) void psum_red_kernel()
{
    const int i = blockIdx.x * 256 + threadIdx.x;
    const int z = i >> 6, d = i & 63;
    float s = 0.f;
#pragma unroll
    for (int g = 0; g < 8; g++) s += g_psumP[z][g][d];
    g_psum[z * 64 + d] = s;
}

// ===========================================================================
// dots = scale*(Qh+Ql)@Kh^T (+col mask) on COMPACTED rows -> pre
// (round-13 proven layout: MMA guarded by row0<cnt, register-direct epilogue)
// ===========================================================================
#define DSTAGE 24576u
#define DOTS_SMEM (4 * 24576)

__global__ __launch_bounds__(256, 2) void dots_gemm(float* __restrict__ Out)
{
    extern __shared__ char sm[];
    __shared__ int cmask[128];
    const uint32_t sbase = smem_u32(sm);

    const int tid = threadIdx.x;
    const int wid = tid >> 5, lane = tid & 31;
    const int wm = wid >> 2, wn = wid & 3;
    const int z = blockIdx.z, b = z >> 3;
    const int row0 = blockIdx.y * 128, col0 = blockIdx.x * 128;

    const int cnt = g_validcnt[b];

    float acc[4][4][4];

    if (row0 < cnt) {
        if (tid < 128) cmask[tid] = g_mask[b * NN + col0 + tid];

        const char* qhB = (const char*)g_qh + (((size_t)z * 16 + blockIdx.y) * 16) * 8192;
        const char* qlB = (const char*)g_ql + (((size_t)z * 16 + blockIdx.y) * 16) * 8192;
        const char* khB = (const char*)g_kh + (((size_t)z * 16 + blockIdx.x) * 16) * 8192;

#pragma unroll
        for (int mf = 0; mf < 4; mf++)
#pragma unroll
            for (int nf = 0; nf < 4; nf++)
#pragma unroll
                for (int r = 0; r < 4; r++) acc[mf][nf][r] = 0.f;

        auto issue = [&](int ch) {
            const uint32_t ss = sbase + (uint32_t)(ch & 3) * DSTAGE;
            const char* q1 = qhB + (size_t)ch * 8192;
            const char* l1 = qlB + (size_t)ch * 8192;
            const char* k1 = khB + (size_t)ch * 8192;
#pragma unroll
            for (int k = 0; k < 2; k++) {
                uint32_t off = (uint32_t)(tid + k * 256) * 16;
                CP16(ss + off,         q1 + off);
                CP16(ss + 8192 + off,  l1 + off);
                CP16(ss + 16384 + off, k1 + off);
            }
        };

        issue(0); CP_COMMIT();
        issue(1); CP_COMMIT();
        issue(2); CP_COMMIT();

        const uint32_t a_row = (uint32_t)(wm * 64) + (lane & 15);
        const uint32_t a_kb  = ((lane >> 4) & 1) * 16;
        const uint32_t b_row = (uint32_t)(wn * 32) + ((lane >> 4) & 1) * 8 + (lane & 7);
        const uint32_t b_kb  = ((lane >> 3) & 1) * 16;

        for (int ch = 0; ch < 16; ++ch) {
            CP_WAIT2();
            __syncthreads();
            const uint32_t S = sbase + (uint32_t)(ch & 3) * DSTAGE;
            const uint32_t AH = S, AL = S + 8192, BH = S + 16384;
#pragma unroll
            for (int ks = 0; ks < 2; ks++) {
                const uint32_t kb0 = (uint32_t)ks * 32;
                uint32_t bh[4][2];
#pragma unroll
                for (int p = 0; p < 2; p++) {
                    uint32_t o = swz(b_row + p * 16, kb0 + b_kb);
                    uint32_t t4[4];
                    ldsm_x4(t4, BH + o);
                    bh[2*p][0] = t4[0]; bh[2*p][1] = t4[1];
                    bh[2*p+1][0] = t4[2]; bh[2*p+1][1] = t4[3];
                }
#pragma unroll
                for (int mf = 0; mf < 4; mf++) {
                    uint32_t o = swz(a_row + mf * 16, kb0 + a_kb);
                    uint32_t ah[4], al[4];
                    ldsm_x4(ah, AH + o);
                    ldsm_x4(al, AL + o);
#pragma unroll
                    for (int nf = 0; nf < 4; nf++) {
                        mma_f16(acc[mf][nf], ah, bh[nf]);
                        mma_f16(acc[mf][nf], al, bh[nf]);
                    }
                }
            }
            if (ch + 3 < 16) issue(ch + 3);
            CP_COMMIT();
        }
    }

    // epilogue: valid rows -> scaled/masked result; rows >= cnt -> MASKV fill
    const int r_lo = row0 + wm * 64 + (lane >> 2);
    const int c_base = wn * 32 + (lane & 3) * 2;
    float* outz = Out + (size_t)z * NN * NN;
#pragma unroll
    for (int mf = 0; mf < 4; mf++) {
#pragma unroll
        for (int rr = 0; rr < 2; rr++) {
            const int cr = r_lo + mf * 16 + rr * 8;
            if (cr < cnt) {
                const int orig = g_rowmap[b][cr];
                float* rowp = outz + (size_t)orig * NN + col0;
#pragma unroll
                for (int nf = 0; nf < 4; nf++) {
                    int cg = c_base + nf * 8;
                    float2 v;
                    v.x = cmask[cg]     ? acc[mf][nf][rr*2+0] * SCALE : MASKV;
                    v.y = cmask[cg + 1] ? acc[mf][nf][rr*2+1] * SCALE : MASKV;
                    __stcs((float2*)(rowp + cg), v);
                }
            } else {
                const int orig = g_maskedmap[b][cr - cnt];
                float* rowp = outz + (size_t)orig * NN + col0;
                const float2 mv = make_float2(MASKV, MASKV);
#pragma unroll
                for (int nf = 0; nf < 4; nf++)
                    __stcs((float2*)(rowp + c_base + nf * 8), mv);
            }
        }
    }
}

// ===========================================================================
// entmax-1.5: streaming loads/stores; Newton with uniform early-exit
// ===========================================================================
__global__ __launch_bounds__(256) void entmax_kernel(
    const float* __restrict__ pre, float* __restrict__ att)
{
    const int wid = threadIdx.x >> 5, lane = threadIdx.x & 31;
    const size_t row = (size_t)blockIdx.x * 8 + wid;
    const int z = (int)(row >> 11), n = (int)(row & 2047), b = z >> 3;
    float4* o4 = (float4*)(att + row * NN);

    if (!g_mask[b * NN + n]) {
        const float P = 1.0f / 2048.0f;
        float4 u = make_float4(P, P, P, P);
#pragma unroll
        for (int i = 0; i < 16; i++) __stcs(&o4[lane + i * 32], u);
        if (lane == 0) g_cnt[row] = -1;
        return;
    }

    const float4* p4 = (const float4*)(pre + row * NN);
    float x[64];
    float mx = -3.0e38f;
#pragma unroll
    for (int i = 0; i < 16; i++) {
        float4 v = __ldcs(&p4[lane + i * 32]);
        x[4*i+0] = 0.5f * v.x; x[4*i+1] = 0.5f * v.y;
        x[4*i+2] = 0.5f * v.z; x[4*i+3] = 0.5f * v.w;
        mx = fmaxf(mx, fmaxf(fmaxf(x[4*i], x[4*i+1]), fmaxf(x[4*i+2], x[4*i+3])));
    }
#pragma unroll
    for (int off = 16; off; off >>= 1)
        mx = fmaxf(mx, __shfl_xor_sync(0xffffffffu, mx, off));
#pragma unroll
    for (int j = 0; j < 64; j++) x[j] -= mx;

    float tau = -1.0f;
#pragma unroll 1
    for (int it = 0; it < 12; ++it) {
        float s1 = 0.f, s2 = 0.f;
#pragma unroll
        for (int j = 0; j < 64; j++) {
            float d = fmaxf(x[j] - tau, 0.f);
            s1 += d;
            s2 = fmaf(d, d, s2);
        }
#pragma unroll
        for (int off = 16; off; off >>= 1) {
            s1 += __shfl_xor_sync(0xffffffffu, s1, off);
            s2 += __shfl_xor_sync(0xffffffffu, s2, off);
        }
        float step = (s1 > 1e-20f) ? (s2 - 1.0f) / (2.0f * s1) : 0.f;
        tau += step;
        if (fabsf(step) < 1e-6f) break;
    }

#pragma unroll
    for (int i = 0; i < 16; i++) {
        float4 w;
        float d;
        d = fmaxf(x[4*i+0] - tau, 0.f); w.x = d * d;
        d = fmaxf(x[4*i+1] - tau, 0.f); w.y = d * d;
        d = fmaxf(x[4*i+2] - tau, 0.f); w.z = d * d;
        d = fmaxf(x[4*i+3] - tau, 0.f); w.w = d * d;
        __stcs(&o4[lane + i * 32], w);
    }

    int cl = 0;
#pragma unroll
    for (int j = 0; j < 64; j++) cl += (x[j] > tau) ? 1 : 0;
    int v = cl;
#pragma unroll
    for (int d = 1; d < 32; d <<= 1) {
        int t = __shfl_up_sync(0xffffffffu, v, d);
        if (lane >= d) v += t;
    }
    int total = __shfl_sync(0xffffffffu, v, 31);
    int pos = v - cl;
    if (total <= MAXS) {
        int*   si = g_si + row * MAXS;
        float* sw = g_sw + row * MAXS;
#pragma unroll
        for (int i = 0; i < 16; i++)
#pragma unroll
            for (int c = 0; c < 4; c++) {
                int j = 4*i + c;
                if (x[j] > tau) {
                    float d = x[j] - tau;
                    si[pos] = 4*lane + 128*i + c;
                    sw[pos] = d * d;
                    pos++;
                }
            }
        if (lane == 31) g_cnt[row] = total;
    } else if (lane == 31) {
        g_cnt[row] = -2;
    }
}

// ===========================================================================
// Fused sparse attention-out: 4-wide unrolled gather (prefetched idx/weights)
// ===========================================================================
__global__ __launch_bounds__(256) void af_kernel(
    const float* __restrict__ att, const float* __restrict__ bo, float* __restrict__ out)
{
    const int wid = threadIdx.x >> 5, lane = threadIdx.x & 31;
    const int gw = blockIdx.x * 8 + wid;
    const int b = gw >> 11, n = gw & 2047;
    const int dc = lane * 2;

    float2 acc;
    float2 bb = *(const float2*)(bo + dc);
    acc.x = bb.x; acc.y = bb.y;

#pragma unroll 1
    for (int h = 0; h < HH; h++) {
        const int z = b * HH + h;
        const size_t row = (size_t)z * NN + n;
        const int cnt = g_cnt[row];
        const float* Pz = g_p + (size_t)z * NN * 64;
        if (cnt == -1) {
            const float Pu = 1.0f / 2048.0f;
            float2 s = *(const float2*)(g_psum + z * 64 + dc);
            acc.x = fmaf(Pu, s.x, acc.x);
            acc.y = fmaf(Pu, s.y, acc.y);
        } else if (cnt >= 0) {
            const int*   si = g_si + row * MAXS;
            const float* sw = g_sw + row * MAXS;
            int j = 0;
            for (; j + 4 <= cnt; j += 4) {
                int   i0 = si[j],   i1 = si[j+1], i2 = si[j+2], i3 = si[j+3];
                float w0 = sw[j],   w1 = sw[j+1], w2 = sw[j+2], w3 = sw[j+3];
                float2 v0 = *(const float2*)(Pz + (size_t)i0 * 64 + dc);
                float2 v1 = *(const float2*)(Pz + (size_t)i1 * 64 + dc);
                float2 v2 = *(const float2*)(Pz + (size_t)i2 * 64 + dc);
                float2 v3 = *(const float2*)(Pz + (size_t)i3 * 64 + dc);
                acc.x = fmaf(w0, v0.x, acc.x); acc.y = fmaf(w0, v0.y, acc.y);
                acc.x = fmaf(w1, v1.x, acc.x); acc.y = fmaf(w1, v1.y, acc.y);
                acc.x = fmaf(w2, v2.x, acc.x); acc.y = fmaf(w2, v2.y, acc.y);
                acc.x = fmaf(w3, v3.x, acc.x); acc.y = fmaf(w3, v3.y, acc.y);
            }
            for (; j < cnt; j++) {
                int   i0 = si[j];
                float w0 = sw[j];
                float2 v0 = *(const float2*)(Pz + (size_t)i0 * 64 + dc);
                acc.x = fmaf(w0, v0.x, acc.x);
                acc.y = fmaf(w0, v0.y, acc.y);
            }
        } else {
            const float* arow = att + row * NN;
            for (int c = 0; c < NN; c++) {
                float p = __ldcs(arow + c);
                if (p != 0.f) {
                    float2 v = *(const float2*)(Pz + (size_t)c * 64 + dc);
                    acc.x = fmaf(p, v.x, acc.x);
                    acc.y = fmaf(p, v.y, acc.y);
                }
            }
        }
    }
    *(float2*)(out + (size_t)gw * 64 + dc) = acc;
}

// ===========================================================================
extern "C" void kernel_launch(void* const* d_in, const int* in_sizes, int n_in,
                              void* d_out, int out_size)
{
    const float* x   = (const float*)d_in[0];
    const unsigned char* mask_raw = (const unsigned char*)d_in[1];
    const float* Wq  = (const float*)d_in[2];
    const float* Wk  = (const float*)d_in[3];
    const float* Wv  = (const float*)d_in[4];
    const float* Wo  = (const float*)d_in[5];
    const float* bo  = (const float*)d_in[6];

    float* out = (float*)d_out;
    float* pre = out + OUT_ELEMS;
    float* att = pre + PRE_ELEMS;

    static cudaStream_t s2 = nullptr;
    static cudaEvent_t ev_fork = nullptr, ev_join = nullptr;
    static int smem_set = 0;
    if (!smem_set) {
        cudaFuncSetAttribute(dots_gemm,
                             cudaFuncAttributeMaxDynamicSharedMemorySize, DOTS_SMEM);
        cudaFuncSetAttribute(proj_mma,
                             cudaFuncAttributeMaxDynamicSharedMemorySize, PROJ_SMEM);
        cudaFuncSetAttribute(pvw_mma,
                             cudaFuncAttributeMaxDynamicSharedMemorySize, PVW_SMEM);
        cudaStreamCreateWithFlags(&s2, cudaStreamNonBlocking);
        cudaEventCreateWithFlags(&ev_fork, cudaEventDisableTiming);
        cudaEventCreateWithFlags(&ev_join, cudaEventDisableTiming);
        smem_set = 1;
    }

    prep_compact_kernel<<<1, 256>>>(mask_raw);

    conv_all_kernel<<<1088, 256>>>(x, Wq, Wk, Wv, Wo);

    proj_mma<<<dim3(96, 32), 256, PROJ_SMEM>>>();

    // fork: pvw + psum run on s2, overlapped with dots on the main stream
    cudaEventRecord(ev_fork, 0);
    cudaStreamWaitEvent(s2, ev_fork, 0);

    pvw_mma<<<dim3(16, 16), 256, PVW_SMEM, s2>>>();
    psum_part_kernel<<<dim3(16, 8), 256, 0, s2>>>();
    psum_red_kernel<<<4, 256, 0, s2>>>();
    cudaEventRecord(ev_join, s2);

    dots_gemm<<<dim3(16, 16, 16), 256, DOTS_SMEM>>>(pre);

    entmax_kernel<<<BB * HH * NN / 8, 256>>>(pre, att);

    // join before af (af reads g_p / g_psum produced on s2)
    cudaStreamWaitEvent(0, ev_join, 0);
    af_kernel<<<BB * NN / 8, 256>>>(att, bo, out);
}